// round 9
// baseline (speedup 1.0000x reference)
#include <cuda_runtime.h>
#include <cstdint>
#include <math.h>

#define B_DIM 2
#define H_DIM 16
#define S_DIM 2048
#define E_DIM 1024

// Scratch (allocation-free rule: device globals)
__device__ float g_Q[B_DIM*H_DIM*S_DIM*64];   // [bh][s][d]
__device__ float g_K[B_DIM*H_DIM*S_DIM*64];
__device__ float g_V[B_DIM*H_DIM*S_DIM*64];
__device__ float g_AV[B_DIM*S_DIM*E_DIM];     // [b][s][h*64+d]

// ===========================================================================
// bf16 mma.sync helpers (base PTX, sm_80+)
// ===========================================================================
__device__ __forceinline__ uint32_t pack_bf16(float lo, float hi) {
  uint32_t r;  // PTX: first src -> upper half, second src -> lower half
  asm("cvt.rn.satfinite.bf16x2.f32 %0, %1, %2;" : "=r"(r) : "f"(hi), "f"(lo));
  return r;
}
__device__ __forceinline__ float lo_f(uint32_t u) {
  return __uint_as_float(u << 16);
}
__device__ __forceinline__ float hi_f(uint32_t u) {
  return __uint_as_float(u & 0xFFFF0000u);
}
__device__ __forceinline__ void split3(float fe, float fo,
                                       uint32_t& h, uint32_t& m, uint32_t& l) {
  h = pack_bf16(fe, fo);
  float re = fe - lo_f(h);
  float ro = fo - hi_f(h);
  m = pack_bf16(re, ro);
  l = pack_bf16(re - lo_f(m), ro - hi_f(m));
}
__device__ __forceinline__ void mma_bf16(float* c, const uint32_t* a,
                                         uint32_t b0, uint32_t b1) {
  asm volatile(
      "mma.sync.aligned.m16n8k16.row.col.f32.bf16.bf16.f32 "
      "{%0,%1,%2,%3},{%4,%5,%6,%7},{%8,%9},{%0,%1,%2,%3};"
      : "+f"(c[0]), "+f"(c[1]), "+f"(c[2]), "+f"(c[3])
      : "r"(a[0]), "r"(a[1]), "r"(a[2]), "r"(a[3]), "r"(b0), "r"(b1));
}

// ===========================================================================
// JAX partitionable-threefry random bits, key (0, 42).
// ===========================================================================
__device__ __forceinline__ uint32_t jax_bits_k42(uint32_t idx) {
  const uint32_t ks0 = 0u;
  const uint32_t ks1 = 42u;
  const uint32_t ks2 = 42u ^ 0x1BD11BDAu;
  uint32_t x0 = ks0;
  uint32_t x1 = idx + ks1;
#define TF_ROUND(r) { x0 += x1; x1 = __funnelshift_l(x1, x1, (r)); x1 ^= x0; }
  TF_ROUND(13) TF_ROUND(15) TF_ROUND(26) TF_ROUND(6)
  x0 += ks1; x1 += ks2 + 1u;
  TF_ROUND(17) TF_ROUND(29) TF_ROUND(16) TF_ROUND(24)
  x0 += ks2; x1 += ks0 + 2u;
  TF_ROUND(13) TF_ROUND(15) TF_ROUND(26) TF_ROUND(6)
  x0 += ks0; x1 += ks1 + 3u;
  TF_ROUND(17) TF_ROUND(29) TF_ROUND(16) TF_ROUND(24)
  x0 += ks1; x1 += ks2 + 4u;
  TF_ROUND(13) TF_ROUND(15) TF_ROUND(26) TF_ROUND(6)
  x0 += ks2; x1 += ks0 + 5u;
#undef TF_ROUND
  return x0 ^ x1;
}

// ===========================================================================
// Tensor QKV GEMM with SEGMENTED accumulation (RZ-bias bounded):
//   c-fragment chains limited to 4 k16 chunks (24 MMA ops — proven safe in
//   r8's QK), folded into fp32 register accumulators with RN FADD.
// CTA 128x64, 8 warps (4m x 2n), warp tile 32x32, BK=16.
// SIX=1 (Q,K cols): 6-product split. SIX=0 (V cols): 3-product split.
// Scatters into g_Q/g_K/g_V per-head layout.
// ===========================================================================
template<int SIX>
__global__ void __launch_bounds__(256)
qkv_tc(const float* __restrict__ A, const float* __restrict__ W,
       const float* __restrict__ bias, int ncol0) {
  __shared__ float As[16][132];
  __shared__ float Ws[16][68];
  const int tid  = threadIdx.x;
  const int lane = tid & 31;
  const int warp = tid >> 5;
  const int g    = lane >> 2;
  const int tg   = lane & 3;
  const int wm   = warp & 3;    // 32-row group
  const int wn   = warp >> 2;   // 32-col group
  const int m0   = blockIdx.y << 7;
  const int n0   = blockIdx.x << 6;   // local col offset in this range

  const int lm = tid & 127;
  const int lk = (tid >> 7) << 3;
  const float* Ap = A + (size_t)(m0 + lm) * 1024 + lk;
  const int lmw = tid & 63;
  const int lkw = (tid >> 6) << 2;
  const float* Wp = W + (size_t)(ncol0 + n0 + lmw) * 1024 + lkw;

  float acc[2][4][4];   // true fp32 accumulators (RN folds)
  float c[2][4][4];     // mma fragments (RZ, short chains)
#pragma unroll
  for (int mt = 0; mt < 2; mt++)
#pragma unroll
    for (int nt = 0; nt < 4; nt++)
#pragma unroll
      for (int r = 0; r < 4; r++) { acc[mt][nt][r] = 0.0f; c[mt][nt][r] = 0.0f; }

  float4 av0 = *(const float4*)Ap;
  float4 av1 = *(const float4*)(Ap + 4);
  float4 wv  = *(const float4*)Wp;

  for (int seg = 0; seg < 16; seg++) {
#pragma unroll
    for (int it = 0; it < 4; it++) {
      const int k0 = (seg*4 + it) << 4;
      As[lk+0][lm] = av0.x; As[lk+1][lm] = av0.y;
      As[lk+2][lm] = av0.z; As[lk+3][lm] = av0.w;
      As[lk+4][lm] = av1.x; As[lk+5][lm] = av1.y;
      As[lk+6][lm] = av1.z; As[lk+7][lm] = av1.w;
      Ws[lkw+0][lmw] = wv.x; Ws[lkw+1][lmw] = wv.y;
      Ws[lkw+2][lmw] = wv.z; Ws[lkw+3][lmw] = wv.w;
      __syncthreads();
      if (k0 + 16 < 1024) {
        av0 = *(const float4*)(Ap + k0 + 16);
        av1 = *(const float4*)(Ap + k0 + 20);
        wv  = *(const float4*)(Wp + k0 + 16);
      }

      uint32_t Ah[2][4], Am[2][4], Al[2][4];
#pragma unroll
      for (int mt = 0; mt < 2; mt++) {
        const int r0 = wm*32 + mt*16 + g;
        const int ke = 2*tg;
#pragma unroll
        for (int p = 0; p < 4; p++) {
          const int kk = ke + ((p & 2) ? 8 : 0);
          const int rr = r0 + ((p & 1) ? 8 : 0);
          split3(As[kk][rr], As[kk+1][rr], Ah[mt][p], Am[mt][p], Al[mt][p]);
        }
      }

#pragma unroll
      for (int nt = 0; nt < 4; nt++) {
        const int n = wn*32 + nt*8 + g;
        const int ke = 2*tg;
        uint32_t Bh0, Bm0, Bl0, Bh1, Bm1, Bl1;
        split3(Ws[ke][n],   Ws[ke+1][n], Bh0, Bm0, Bl0);
        split3(Ws[ke+8][n], Ws[ke+9][n], Bh1, Bm1, Bl1);
#pragma unroll
        for (int mt = 0; mt < 2; mt++) {
          mma_bf16(c[mt][nt], Ah[mt], Bh0, Bh1);    // hh
          mma_bf16(c[mt][nt], Ah[mt], Bm0, Bm1);    // hm
          mma_bf16(c[mt][nt], Am[mt], Bh0, Bh1);    // mh
          if (SIX) {
            mma_bf16(c[mt][nt], Ah[mt], Bl0, Bl1);  // hl
            mma_bf16(c[mt][nt], Am[mt], Bm0, Bm1);  // mm
            mma_bf16(c[mt][nt], Al[mt], Bh0, Bh1);  // lh
          }
        }
      }
      __syncthreads();
    }
    // fold segment into RN accumulators, restart fragment chain
#pragma unroll
    for (int mt = 0; mt < 2; mt++)
#pragma unroll
      for (int nt = 0; nt < 4; nt++)
#pragma unroll
        for (int r = 0; r < 4; r++) {
          acc[mt][nt][r] += c[mt][nt][r];
          c[mt][nt][r] = 0.0f;
        }
  }

  // Epilogue: scatter into g_Q/g_K/g_V
#pragma unroll
  for (int nt = 0; nt < 4; nt++) {
    const int col = ncol0 + n0 + wn*32 + nt*8 + tg*2;
    const float bx = bias[col], by = bias[col+1];
    const int t  = col >> 10;
    const int hh = (col >> 6) & 15;
    const int d0 = col & 63;
    float* dst = (t == 0) ? g_Q : (t == 1) ? g_K : g_V;
#pragma unroll
    for (int mt = 0; mt < 2; mt++) {
      const int row = m0 + wm*32 + mt*16 + g;
      const int bb = row >> 11;
      const int s  = row & 2047;
      size_t base = (((size_t)bb * H_DIM + hh) * S_DIM + s) * 64 + d0;
      *(float2*)&dst[base] =
          make_float2(acc[mt][nt][0] + bx, acc[mt][nt][1] + by);
      *(float2*)&dst[base + 8*64] =
          make_float2(acc[mt][nt][2] + bx, acc[mt][nt][3] + by);
    }
  }
}

// ===========================================================================
// bf16x3 tensor GEMM for the output projection (proven r7/r8).
// ===========================================================================
__global__ void __launch_bounds__(256, 2)
bf16_proj(const float* __restrict__ A, const float* __restrict__ W,
          const float* __restrict__ bias, float* __restrict__ C) {
  __shared__ float As[16][132];
  __shared__ float Ws[16][132];
  const int tid  = threadIdx.x;
  const int lane = tid & 31;
  const int warp = tid >> 5;
  const int g    = lane >> 2;
  const int tg   = lane & 3;
  const int wm   = warp & 3;
  const int wn   = warp >> 2;
  const int m0   = blockIdx.y << 7;
  const int n0   = blockIdx.x << 7;

  const int lm = tid & 127;
  const int lk = (tid >> 7) << 3;
  const float* Ap = A + (size_t)(m0 + lm) * 1024 + lk;
  const float* Wp = W + (size_t)(n0 + lm) * 1024 + lk;

  float c[2][8][4];
#pragma unroll
  for (int mt = 0; mt < 2; mt++)
#pragma unroll
    for (int nt = 0; nt < 8; nt++)
#pragma unroll
      for (int r = 0; r < 4; r++) c[mt][nt][r] = 0.0f;

  float4 av0 = *(const float4*)Ap;
  float4 av1 = *(const float4*)(Ap + 4);
  float4 wv0 = *(const float4*)Wp;
  float4 wv1 = *(const float4*)(Wp + 4);

  for (int k0 = 0; k0 < 1024; k0 += 16) {
    As[lk+0][lm] = av0.x; As[lk+1][lm] = av0.y;
    As[lk+2][lm] = av0.z; As[lk+3][lm] = av0.w;
    As[lk+4][lm] = av1.x; As[lk+5][lm] = av1.y;
    As[lk+6][lm] = av1.z; As[lk+7][lm] = av1.w;
    Ws[lk+0][lm] = wv0.x; Ws[lk+1][lm] = wv0.y;
    Ws[lk+2][lm] = wv0.z; Ws[lk+3][lm] = wv0.w;
    Ws[lk+4][lm] = wv1.x; Ws[lk+5][lm] = wv1.y;
    Ws[lk+6][lm] = wv1.z; Ws[lk+7][lm] = wv1.w;
    __syncthreads();
    if (k0 + 16 < 1024) {
      av0 = *(const float4*)(Ap + k0 + 16);
      av1 = *(const float4*)(Ap + k0 + 20);
      wv0 = *(const float4*)(Wp + k0 + 16);
      wv1 = *(const float4*)(Wp + k0 + 20);
    }

    uint32_t Ah[2][4], Am[2][4], Al[2][4];
#pragma unroll
    for (int mt = 0; mt < 2; mt++) {
      const int r0 = wm*32 + mt*16 + g;
      const int ke = 2*tg;
#pragma unroll
      for (int p = 0; p < 4; p++) {
        const int kk = ke + ((p & 2) ? 8 : 0);
        const int rr = r0 + ((p & 1) ? 8 : 0);
        split3(As[kk][rr], As[kk+1][rr], Ah[mt][p], Am[mt][p], Al[mt][p]);
      }
    }

#pragma unroll
    for (int nt = 0; nt < 8; nt++) {
      const int n = wn*64 + nt*8 + g;
      const int ke = 2*tg;
      uint32_t Bh0, Bm0, Bl0, Bh1, Bm1, Bl1;
      split3(Ws[ke][n],   Ws[ke+1][n], Bh0, Bm0, Bl0);
      split3(Ws[ke+8][n], Ws[ke+9][n], Bh1, Bm1, Bl1);
#pragma unroll
      for (int mt = 0; mt < 2; mt++) {
        mma_bf16(c[mt][nt], Ah[mt], Bh0, Bh1);   // hh
        mma_bf16(c[mt][nt], Ah[mt], Bm0, Bm1);   // hm
        mma_bf16(c[mt][nt], Am[mt], Bh0, Bh1);   // mh
      }
    }
    __syncthreads();
  }

#pragma unroll
  for (int nt = 0; nt < 8; nt++) {
    const int col = n0 + wn*64 + nt*8 + tg*2;
    const float bx = bias[col], by = bias[col+1];
#pragma unroll
    for (int mt = 0; mt < 2; mt++) {
      const int row = m0 + wm*32 + mt*16 + g;
      *(float2*)&C[(size_t)row     * E_DIM + col] =
          make_float2(c[mt][nt][0] + bx, c[mt][nt][1] + by);
      *(float2*)&C[(size_t)(row+8) * E_DIM + col] =
          make_float2(c[mt][nt][2] + bx, c[mt][nt][3] + by);
    }
  }
}

// ===========================================================================
// Fused attention (proven r8): bf16x6 QK + threefry + bf16x2 PV
// ===========================================================================
#define QS_STRIDE 72
#define KH_OFF  9216
#define KM_OFF  (KH_OFF + 2304)
#define KL_OFF  (KM_OFF + 2304)
#define PP_OFF  (KL_OFF + 2304)
#define VH_OFF  (PP_OFF + 4608)
#define VL_OFF  (VH_OFF + 2304)
#define ATTN_SMEM ((VL_OFF + 2304) * 4)   // 101376 bytes

__global__ void __launch_bounds__(256, 2)
attn_kernel(float* __restrict__ gAV) {
  extern __shared__ float smf[];
  float*    Qs = smf;                          // [q][72] fp32
  uint32_t* Kh = (uint32_t*)(smf + KH_OFF);    // [k][36]
  uint32_t* Km = (uint32_t*)(smf + KM_OFF);
  uint32_t* Kl = (uint32_t*)(smf + KL_OFF);
  uint32_t* Pp = (uint32_t*)(smf + PP_OFF);    // [q][36] packed k-pairs
  uint32_t* Vh = (uint32_t*)(smf + VH_OFF);    // [d][36] packed k-pairs
  uint32_t* Vl = (uint32_t*)(smf + VL_OFF);

  const int tid  = threadIdx.x;
  const int lane = tid & 31;
  const int warp = tid >> 5;
  const int g    = lane >> 2;
  const int tg   = lane & 3;
  const int bh   = blockIdx.y;
  const int b    = bh >> 4;
  const int h    = bh & 15;
  const int q0   = blockIdx.x << 7;

  const int wq = warp & 3;
  const int wk = warp >> 2;
  const int wm2 = warp & 3;
  const int wn2 = warp >> 2;

  const float* Qg = g_Q + ((size_t)bh * S_DIM + q0) * 64;
  const float* Kg = g_K + (size_t)bh * S_DIM * 64;
  const float* Vg = g_V + (size_t)bh * S_DIM * 64;

  {
#pragma unroll
    for (int i = 0; i < 8; i++) {
      const int idx = tid + i*256;
      const int row = idx >> 4;
      const int c4  = idx & 15;
      float4 v = *(const float4*)&Qg[(size_t)row*64 + c4*4];
      *(float4*)&Qs[row*QS_STRIDE + c4*4] = v;
    }
  }

  float co[2][4][4];
#pragma unroll
  for (int mt = 0; mt < 2; mt++)
#pragma unroll
    for (int nt = 0; nt < 4; nt++)
#pragma unroll
      for (int r = 0; r < 4; r++) co[mt][nt][r] = 0.0f;

  const uint32_t cbase = ((uint32_t)bh << 11) + (uint32_t)q0;

  for (int kt = 0; kt < 32; kt++) {
    __syncthreads();

    {
      const int r = tid >> 2;
      const float* krow = &Kg[(size_t)(kt*64 + r)*64];
      const int base = r*36;
#pragma unroll
      for (int i = 0; i < 4; i++) {
        const int d4 = (tid & 3)*4 + i;
        float4 v = *(const float4*)&krow[d4*4];
        uint32_t h0, m0_, l0, h1, m1, l1;
        split3(v.x, v.y, h0, m0_, l0);
        split3(v.z, v.w, h1, m1, l1);
        Kh[base + d4*2]     = h0;  Km[base + d4*2]     = m0_;  Kl[base + d4*2]     = l0;
        Kh[base + d4*2 + 1] = h1;  Km[base + d4*2 + 1] = m1;  Kl[base + d4*2 + 1] = l1;
      }
    }
    {
#pragma unroll
      for (int r = 0; r < 2; r++) {
        const int w  = tid + r*256;
        const int kp = w & 31;
        const int d0 = (w >> 5) * 4;
        const float* v0 = &Vg[(size_t)(kt*64 + 2*kp)*64 + d0];
        float4 a = *(const float4*)v0;
        float4 bvv = *(const float4*)(v0 + 64);
        float va[4] = {a.x, a.y, a.z, a.w};
        float vb[4] = {bvv.x, bvv.y, bvv.z, bvv.w};
#pragma unroll
        for (int e = 0; e < 4; e++) {
          uint32_t hp = pack_bf16(va[e], vb[e]);
          uint32_t lp = pack_bf16(va[e] - lo_f(hp), vb[e] - hi_f(hp));
          Vh[(d0+e)*36 + kp] = hp;
          Vl[(d0+e)*36 + kp] = lp;
        }
      }
    }
    __syncthreads();

    float c[2][4][4];
#pragma unroll
    for (int mt = 0; mt < 2; mt++)
#pragma unroll
      for (int nt = 0; nt < 4; nt++)
#pragma unroll
        for (int r = 0; r < 4; r++) c[mt][nt][r] = 0.0f;

#pragma unroll
    for (int c4 = 0; c4 < 4; c4++) {
      const int k0 = c4*16 + 2*tg;
      uint32_t Ah[2][4], Am[2][4], Al[2][4];
#pragma unroll
      for (int mt = 0; mt < 2; mt++) {
        const float* q0p = &Qs[(wq*32 + mt*16 + g)*QS_STRIDE];
        const float* q8p = q0p + 8*QS_STRIDE;
        float2 v00 = *(const float2*)&q0p[k0];
        float2 v01 = *(const float2*)&q8p[k0];
        float2 v10 = *(const float2*)&q0p[k0+8];
        float2 v11 = *(const float2*)&q8p[k0+8];
        split3(v00.x, v00.y, Ah[mt][0], Am[mt][0], Al[mt][0]);
        split3(v01.x, v01.y, Ah[mt][1], Am[mt][1], Al[mt][1]);
        split3(v10.x, v10.y, Ah[mt][2], Am[mt][2], Al[mt][2]);
        split3(v11.x, v11.y, Ah[mt][3], Am[mt][3], Al[mt][3]);
      }
#pragma unroll
      for (int nt = 0; nt < 4; nt++) {
        const int col = wk*32 + nt*8 + g;
        const int kb  = col*36 + c4*8;
        uint32_t Bh0 = Kh[kb+tg], Bh1 = Kh[kb+tg+4];
        uint32_t Bm0 = Km[kb+tg], Bm1 = Km[kb+tg+4];
        uint32_t Bl0 = Kl[kb+tg], Bl1 = Kl[kb+tg+4];
#pragma unroll
        for (int mt = 0; mt < 2; mt++) {
          mma_bf16(c[mt][nt], Ah[mt], Bh0, Bh1);
          mma_bf16(c[mt][nt], Ah[mt], Bm0, Bm1);
          mma_bf16(c[mt][nt], Am[mt], Bh0, Bh1);
          mma_bf16(c[mt][nt], Ah[mt], Bl0, Bl1);
          mma_bf16(c[mt][nt], Am[mt], Bm0, Bm1);
          mma_bf16(c[mt][nt], Al[mt], Bh0, Bh1);
        }
      }
    }

    const uint32_t ktk = (uint32_t)(kt*64);
#pragma unroll
    for (int mt = 0; mt < 2; mt++) {
      const int qA = wq*32 + mt*16 + g;
      const uint32_t row0 = (cbase + (uint32_t)qA) << 11;
      const uint32_t row8 = (cbase + (uint32_t)(qA+8)) << 11;
#pragma unroll
      for (int nt = 0; nt < 4; nt++) {
        const uint32_t kl = ktk + (uint32_t)(wk*32 + nt*8 + 2*tg);
        float p0 = 1.0f / (1.0f + expf(-c[mt][nt][0] * 0.125f));
        float p1 = 1.0f / (1.0f + expf(-c[mt][nt][1] * 0.125f));
        float p2 = 1.0f / (1.0f + expf(-c[mt][nt][2] * 0.125f));
        float p3 = 1.0f / (1.0f + expf(-c[mt][nt][3] * 0.125f));
        uint32_t b0 = jax_bits_k42(row0 + kl);
        uint32_t b1 = jax_bits_k42(row0 + kl + 1u);
        uint32_t b2 = jax_bits_k42(row8 + kl);
        uint32_t b3 = jax_bits_k42(row8 + kl + 1u);
        float u0 = __uint_as_float((b0 >> 9) | 0x3f800000u) - 1.0f;
        float u1 = __uint_as_float((b1 >> 9) | 0x3f800000u) - 1.0f;
        float u2 = __uint_as_float((b2 >> 9) | 0x3f800000u) - 1.0f;
        float u3 = __uint_as_float((b3 >> 9) | 0x3f800000u) - 1.0f;
        const int kp = wk*16 + nt*4 + tg;
        Pp[qA*36 + kp]     = pack_bf16(u0 < p0 ? 1.0f : 0.0f,
                                       u1 < p1 ? 1.0f : 0.0f);
        Pp[(qA+8)*36 + kp] = pack_bf16(u2 < p2 ? 1.0f : 0.0f,
                                       u3 < p3 ? 1.0f : 0.0f);
      }
    }
    __syncthreads();

#pragma unroll
    for (int c4 = 0; c4 < 4; c4++) {
      uint32_t a[2][4];
#pragma unroll
      for (int mt = 0; mt < 2; mt++) {
        const int row = wm2*32 + mt*16 + g;
        a[mt][0] = Pp[row    *36 + c4*8 + tg];
        a[mt][1] = Pp[(row+8)*36 + c4*8 + tg];
        a[mt][2] = Pp[row    *36 + c4*8 + tg + 4];
        a[mt][3] = Pp[(row+8)*36 + c4*8 + tg + 4];
      }
#pragma unroll
      for (int nt = 0; nt < 4; nt++) {
        const int d = wn2*32 + nt*8 + g;
        uint32_t bh0 = Vh[d*36 + c4*8 + tg];
        uint32_t bh1 = Vh[d*36 + c4*8 + tg + 4];
        uint32_t bl0 = Vl[d*36 + c4*8 + tg];
        uint32_t bl1 = Vl[d*36 + c4*8 + tg + 4];
#pragma unroll
        for (int mt = 0; mt < 2; mt++) {
          mma_bf16(co[mt][nt], a[mt], bh0, bh1);
          mma_bf16(co[mt][nt], a[mt], bl0, bl1);
        }
      }
    }
  }

#pragma unroll
  for (int mt = 0; mt < 2; mt++) {
    const int q = q0 + wm2*32 + mt*16 + g;
#pragma unroll
    for (int nt = 0; nt < 4; nt++) {
      const int d = wn2*32 + nt*8 + tg*2;
      size_t base = ((size_t)(b*S_DIM + q))*E_DIM + h*64 + d;
      *(float2*)&gAV[base] = make_float2(co[mt][nt][0], co[mt][nt][1]);
      *(float2*)&gAV[base + (size_t)8*E_DIM] =
          make_float2(co[mt][nt][2], co[mt][nt][3]);
    }
  }
}

// ===========================================================================
extern "C" void kernel_launch(void* const* d_in, const int* in_sizes, int n_in,
                              void* d_out, int out_size) {
  const float *x = nullptr, *qkv_w = nullptr, *qkv_b = nullptr;
  const float *out_w = nullptr, *out_b = nullptr;
  for (int i = 0; i < n_in; i++) {
    int sz = in_sizes[i];
    if (sz == B_DIM*S_DIM*E_DIM) { if (!x) x = (const float*)d_in[i]; }
    else if (sz == 3*E_DIM*E_DIM) qkv_w = (const float*)d_in[i];
    else if (sz == 3*E_DIM)       qkv_b = (const float*)d_in[i];
    else if (sz == E_DIM*E_DIM)   out_w = (const float*)d_in[i];
    else if (sz == E_DIM)         out_b = (const float*)d_in[i];
  }
  float* out = (float*)d_out;

  float* gav_ptr = nullptr;
  cudaGetSymbolAddress((void**)&gav_ptr, g_AV);

  // 1) QKV: tensor bf16 split, segmented RN accumulation.
  //    Q,K columns (0..2047): x6.  V columns (2048..3071): x3.
  qkv_tc<1><<<dim3(32, 32), 256>>>(x, qkv_w, qkv_b, 0);
  qkv_tc<0><<<dim3(16, 32), 256>>>(x, qkv_w, qkv_b, 2048);

  // 2) fused attention: tensor bf16x6 QK + threefry + tensor bf16x2 PV
  cudaFuncSetAttribute(attn_kernel, cudaFuncAttributeMaxDynamicSharedMemorySize,
                       ATTN_SMEM);
  attn_kernel<<<dim3(S_DIM/128, B_DIM*H_DIM), 256, ATTN_SMEM>>>(gav_ptr);

  // 3) out = AV @ out_w^T + out_b — tensor bf16x3
  bf16_proj<<<dim3(E_DIM/128, (B_DIM*S_DIM)/128), 256>>>(
      gav_ptr, out_w, out_b, out);
}

// round 10
// speedup vs baseline: 1.0425x; 1.0425x over previous
#include <cuda_runtime.h>
#include <cstdint>
#include <math.h>

#define B_DIM 2
#define H_DIM 16
#define S_DIM 2048
#define E_DIM 1024

// Scratch (allocation-free rule: device globals)
__device__ float g_Q[B_DIM*H_DIM*S_DIM*64];   // [bh][s][d]
__device__ float g_K[B_DIM*H_DIM*S_DIM*64];
__device__ float g_V[B_DIM*H_DIM*S_DIM*64];
__device__ float g_AV[B_DIM*S_DIM*E_DIM];     // [b][s][h*64+d]

// ===========================================================================
// bf16 mma.sync helpers (base PTX, sm_80+)
// ===========================================================================
__device__ __forceinline__ uint32_t pack_bf16(float lo, float hi) {
  uint32_t r;  // PTX: first src -> upper half, second src -> lower half
  asm("cvt.rn.satfinite.bf16x2.f32 %0, %1, %2;" : "=r"(r) : "f"(hi), "f"(lo));
  return r;
}
__device__ __forceinline__ float lo_f(uint32_t u) {
  return __uint_as_float(u << 16);
}
__device__ __forceinline__ float hi_f(uint32_t u) {
  return __uint_as_float(u & 0xFFFF0000u);
}
__device__ __forceinline__ void split3(float fe, float fo,
                                       uint32_t& h, uint32_t& m, uint32_t& l) {
  h = pack_bf16(fe, fo);
  float re = fe - lo_f(h);
  float ro = fo - hi_f(h);
  m = pack_bf16(re, ro);
  l = pack_bf16(re - lo_f(m), ro - hi_f(m));
}
__device__ __forceinline__ void mma_bf16(float* c, const uint32_t* a,
                                         uint32_t b0, uint32_t b1) {
  asm volatile(
      "mma.sync.aligned.m16n8k16.row.col.f32.bf16.bf16.f32 "
      "{%0,%1,%2,%3},{%4,%5,%6,%7},{%8,%9},{%0,%1,%2,%3};"
      : "+f"(c[0]), "+f"(c[1]), "+f"(c[2]), "+f"(c[3])
      : "r"(a[0]), "r"(a[1]), "r"(a[2]), "r"(a[3]), "r"(b0), "r"(b1));
}

// ===========================================================================
// JAX partitionable-threefry random bits, key (0, 42).
// ===========================================================================
__device__ __forceinline__ uint32_t jax_bits_k42(uint32_t idx) {
  const uint32_t ks0 = 0u;
  const uint32_t ks1 = 42u;
  const uint32_t ks2 = 42u ^ 0x1BD11BDAu;
  uint32_t x0 = ks0;
  uint32_t x1 = idx + ks1;
#define TF_ROUND(r) { x0 += x1; x1 = __funnelshift_l(x1, x1, (r)); x1 ^= x0; }
  TF_ROUND(13) TF_ROUND(15) TF_ROUND(26) TF_ROUND(6)
  x0 += ks1; x1 += ks2 + 1u;
  TF_ROUND(17) TF_ROUND(29) TF_ROUND(16) TF_ROUND(24)
  x0 += ks2; x1 += ks0 + 2u;
  TF_ROUND(13) TF_ROUND(15) TF_ROUND(26) TF_ROUND(6)
  x0 += ks0; x1 += ks1 + 3u;
  TF_ROUND(17) TF_ROUND(29) TF_ROUND(16) TF_ROUND(24)
  x0 += ks1; x1 += ks2 + 4u;
  TF_ROUND(13) TF_ROUND(15) TF_ROUND(26) TF_ROUND(6)
  x0 += ks2; x1 += ks0 + 5u;
#undef TF_ROUND
  return x0 ^ x1;
}

// ===========================================================================
// Tensor QKV GEMM, segmented accumulation (r9-identical math), now with:
//   __launch_bounds__(256, 2)  -> 2 CTAs/SM (16 warps) for latency hiding
//   double-buffered smem, ONE __syncthreads per BK=16 iteration
// CTA 128x64, 8 warps (4m x 2n), warp tile 32x32.
// SIX=1 (Q,K cols): 6-product split. SIX=0 (V cols): 3-product split.
// ===========================================================================
template<int SIX>
__global__ void __launch_bounds__(256, 2)
qkv_tc(const float* __restrict__ A, const float* __restrict__ W,
       const float* __restrict__ bias, int ncol0) {
  __shared__ float As[2][16][132];
  __shared__ float Ws[2][16][68];
  const int tid  = threadIdx.x;
  const int lane = tid & 31;
  const int warp = tid >> 5;
  const int g    = lane >> 2;
  const int tg   = lane & 3;
  const int wm   = warp & 3;    // 32-row group
  const int wn   = warp >> 2;   // 32-col group
  const int m0   = blockIdx.y << 7;
  const int n0   = blockIdx.x << 6;

  const int lm = tid & 127;
  const int lk = (tid >> 7) << 3;
  const float* Ap = A + (size_t)(m0 + lm) * 1024 + lk;
  const int lmw = tid & 63;
  const int lkw = (tid >> 6) << 2;
  const float* Wp = W + (size_t)(ncol0 + n0 + lmw) * 1024 + lkw;

  float acc[2][4][4];   // fp32 accumulators (RN folds)
  float c[2][4][4];     // mma fragments (RZ, short chains)
#pragma unroll
  for (int mt = 0; mt < 2; mt++)
#pragma unroll
    for (int nt = 0; nt < 4; nt++)
#pragma unroll
      for (int r = 0; r < 4; r++) { acc[mt][nt][r] = 0.0f; c[mt][nt][r] = 0.0f; }

  // stage tile 0 into buffer 0
  {
    float4 a0 = *(const float4*)Ap;
    float4 a1 = *(const float4*)(Ap + 4);
    float4 w0 = *(const float4*)Wp;
    As[0][lk+0][lm] = a0.x; As[0][lk+1][lm] = a0.y;
    As[0][lk+2][lm] = a0.z; As[0][lk+3][lm] = a0.w;
    As[0][lk+4][lm] = a1.x; As[0][lk+5][lm] = a1.y;
    As[0][lk+6][lm] = a1.z; As[0][lk+7][lm] = a1.w;
    Ws[0][lkw+0][lmw] = w0.x; Ws[0][lkw+1][lmw] = w0.y;
    Ws[0][lkw+2][lmw] = w0.z; Ws[0][lkw+3][lmw] = w0.w;
  }
  __syncthreads();

  float4 av0, av1, wv;
  for (int it = 0; it < 64; it++) {
    const int buf = it & 1;
    const int k0  = it << 4;
    if (it + 1 < 64) {
      av0 = *(const float4*)(Ap + k0 + 16);
      av1 = *(const float4*)(Ap + k0 + 20);
      wv  = *(const float4*)(Wp + k0 + 16);
    }

    uint32_t Ah[2][4], Am[2][4], Al[2][4];
#pragma unroll
    for (int mt = 0; mt < 2; mt++) {
      const int r0 = wm*32 + mt*16 + g;
      const int ke = 2*tg;
#pragma unroll
      for (int p = 0; p < 4; p++) {
        const int kk = ke + ((p & 2) ? 8 : 0);
        const int rr = r0 + ((p & 1) ? 8 : 0);
        split3(As[buf][kk][rr], As[buf][kk+1][rr],
               Ah[mt][p], Am[mt][p], Al[mt][p]);
      }
    }

#pragma unroll
    for (int nt = 0; nt < 4; nt++) {
      const int n = wn*32 + nt*8 + g;
      const int ke = 2*tg;
      uint32_t Bh0, Bm0, Bl0, Bh1, Bm1, Bl1;
      split3(Ws[buf][ke][n],   Ws[buf][ke+1][n], Bh0, Bm0, Bl0);
      split3(Ws[buf][ke+8][n], Ws[buf][ke+9][n], Bh1, Bm1, Bl1);
#pragma unroll
      for (int mt = 0; mt < 2; mt++) {
        mma_bf16(c[mt][nt], Ah[mt], Bh0, Bh1);    // hh
        mma_bf16(c[mt][nt], Ah[mt], Bm0, Bm1);    // hm
        mma_bf16(c[mt][nt], Am[mt], Bh0, Bh1);    // mh
        if (SIX) {
          mma_bf16(c[mt][nt], Ah[mt], Bl0, Bl1);  // hl
          mma_bf16(c[mt][nt], Am[mt], Bm0, Bm1);  // mm
          mma_bf16(c[mt][nt], Al[mt], Bh0, Bh1);  // lh
        }
      }
    }

    if (it + 1 < 64) {
      const int nb = buf ^ 1;
      As[nb][lk+0][lm] = av0.x; As[nb][lk+1][lm] = av0.y;
      As[nb][lk+2][lm] = av0.z; As[nb][lk+3][lm] = av0.w;
      As[nb][lk+4][lm] = av1.x; As[nb][lk+5][lm] = av1.y;
      As[nb][lk+6][lm] = av1.z; As[nb][lk+7][lm] = av1.w;
      Ws[nb][lkw+0][lmw] = wv.x; Ws[nb][lkw+1][lmw] = wv.y;
      Ws[nb][lkw+2][lmw] = wv.z; Ws[nb][lkw+3][lmw] = wv.w;
      __syncthreads();
    }

    if ((it & 3) == 3) {   // fold segment (4 k16 chunks) into RN accumulators
#pragma unroll
      for (int mt = 0; mt < 2; mt++)
#pragma unroll
        for (int nt = 0; nt < 4; nt++)
#pragma unroll
          for (int r = 0; r < 4; r++) {
            acc[mt][nt][r] += c[mt][nt][r];
            c[mt][nt][r] = 0.0f;
          }
    }
  }

  // Epilogue: scatter into g_Q/g_K/g_V
#pragma unroll
  for (int nt = 0; nt < 4; nt++) {
    const int col = ncol0 + n0 + wn*32 + nt*8 + tg*2;
    const float bx = bias[col], by = bias[col+1];
    const int t  = col >> 10;
    const int hh = (col >> 6) & 15;
    const int d0 = col & 63;
    float* dst = (t == 0) ? g_Q : (t == 1) ? g_K : g_V;
#pragma unroll
    for (int mt = 0; mt < 2; mt++) {
      const int row = m0 + wm*32 + mt*16 + g;
      const int bb = row >> 11;
      const int s  = row & 2047;
      size_t base = (((size_t)bb * H_DIM + hh) * S_DIM + s) * 64 + d0;
      *(float2*)&dst[base] =
          make_float2(acc[mt][nt][0] + bx, acc[mt][nt][1] + by);
      *(float2*)&dst[base + 8*64] =
          make_float2(acc[mt][nt][2] + bx, acc[mt][nt][3] + by);
    }
  }
}

// ===========================================================================
// bf16x3 tensor GEMM for the output projection (proven r7/r8/r9 — unchanged).
// ===========================================================================
__global__ void __launch_bounds__(256, 2)
bf16_proj(const float* __restrict__ A, const float* __restrict__ W,
          const float* __restrict__ bias, float* __restrict__ C) {
  __shared__ float As[16][132];
  __shared__ float Ws[16][132];
  const int tid  = threadIdx.x;
  const int lane = tid & 31;
  const int warp = tid >> 5;
  const int g    = lane >> 2;
  const int tg   = lane & 3;
  const int wm   = warp & 3;
  const int wn   = warp >> 2;
  const int m0   = blockIdx.y << 7;
  const int n0   = blockIdx.x << 7;

  const int lm = tid & 127;
  const int lk = (tid >> 7) << 3;
  const float* Ap = A + (size_t)(m0 + lm) * 1024 + lk;
  const float* Wp = W + (size_t)(n0 + lm) * 1024 + lk;

  float c[2][8][4];
#pragma unroll
  for (int mt = 0; mt < 2; mt++)
#pragma unroll
    for (int nt = 0; nt < 8; nt++)
#pragma unroll
      for (int r = 0; r < 4; r++) c[mt][nt][r] = 0.0f;

  float4 av0 = *(const float4*)Ap;
  float4 av1 = *(const float4*)(Ap + 4);
  float4 wv0 = *(const float4*)Wp;
  float4 wv1 = *(const float4*)(Wp + 4);

  for (int k0 = 0; k0 < 1024; k0 += 16) {
    As[lk+0][lm] = av0.x; As[lk+1][lm] = av0.y;
    As[lk+2][lm] = av0.z; As[lk+3][lm] = av0.w;
    As[lk+4][lm] = av1.x; As[lk+5][lm] = av1.y;
    As[lk+6][lm] = av1.z; As[lk+7][lm] = av1.w;
    Ws[lk+0][lm] = wv0.x; Ws[lk+1][lm] = wv0.y;
    Ws[lk+2][lm] = wv0.z; Ws[lk+3][lm] = wv0.w;
    Ws[lk+4][lm] = wv1.x; Ws[lk+5][lm] = wv1.y;
    Ws[lk+6][lm] = wv1.z; Ws[lk+7][lm] = wv1.w;
    __syncthreads();
    if (k0 + 16 < 1024) {
      av0 = *(const float4*)(Ap + k0 + 16);
      av1 = *(const float4*)(Ap + k0 + 20);
      wv0 = *(const float4*)(Wp + k0 + 16);
      wv1 = *(const float4*)(Wp + k0 + 20);
    }

    uint32_t Ah[2][4], Am[2][4], Al[2][4];
#pragma unroll
    for (int mt = 0; mt < 2; mt++) {
      const int r0 = wm*32 + mt*16 + g;
      const int ke = 2*tg;
#pragma unroll
      for (int p = 0; p < 4; p++) {
        const int kk = ke + ((p & 2) ? 8 : 0);
        const int rr = r0 + ((p & 1) ? 8 : 0);
        split3(As[kk][rr], As[kk+1][rr], Ah[mt][p], Am[mt][p], Al[mt][p]);
      }
    }

#pragma unroll
    for (int nt = 0; nt < 8; nt++) {
      const int n = wn*64 + nt*8 + g;
      const int ke = 2*tg;
      uint32_t Bh0, Bm0, Bl0, Bh1, Bm1, Bl1;
      split3(Ws[ke][n],   Ws[ke+1][n], Bh0, Bm0, Bl0);
      split3(Ws[ke+8][n], Ws[ke+9][n], Bh1, Bm1, Bl1);
#pragma unroll
      for (int mt = 0; mt < 2; mt++) {
        mma_bf16(c[mt][nt], Ah[mt], Bh0, Bh1);   // hh
        mma_bf16(c[mt][nt], Ah[mt], Bm0, Bm1);   // hm
        mma_bf16(c[mt][nt], Am[mt], Bh0, Bh1);   // mh
      }
    }
    __syncthreads();
  }

#pragma unroll
  for (int nt = 0; nt < 8; nt++) {
    const int col = n0 + wn*64 + nt*8 + tg*2;
    const float bx = bias[col], by = bias[col+1];
#pragma unroll
    for (int mt = 0; mt < 2; mt++) {
      const int row = m0 + wm*32 + mt*16 + g;
      *(float2*)&C[(size_t)row     * E_DIM + col] =
          make_float2(c[mt][nt][0] + bx, c[mt][nt][1] + by);
      *(float2*)&C[(size_t)(row+8) * E_DIM + col] =
          make_float2(c[mt][nt][2] + bx, c[mt][nt][3] + by);
    }
  }
}

// ===========================================================================
// Fused attention (proven r8/r9 — unchanged): bf16x6 QK + threefry + bf16x2 PV
// ===========================================================================
#define QS_STRIDE 72
#define KH_OFF  9216
#define KM_OFF  (KH_OFF + 2304)
#define KL_OFF  (KM_OFF + 2304)
#define PP_OFF  (KL_OFF + 2304)
#define VH_OFF  (PP_OFF + 4608)
#define VL_OFF  (VH_OFF + 2304)
#define ATTN_SMEM ((VL_OFF + 2304) * 4)   // 101376 bytes

__global__ void __launch_bounds__(256, 2)
attn_kernel(float* __restrict__ gAV) {
  extern __shared__ float smf[];
  float*    Qs = smf;                          // [q][72] fp32
  uint32_t* Kh = (uint32_t*)(smf + KH_OFF);    // [k][36]
  uint32_t* Km = (uint32_t*)(smf + KM_OFF);
  uint32_t* Kl = (uint32_t*)(smf + KL_OFF);
  uint32_t* Pp = (uint32_t*)(smf + PP_OFF);    // [q][36] packed k-pairs
  uint32_t* Vh = (uint32_t*)(smf + VH_OFF);    // [d][36] packed k-pairs
  uint32_t* Vl = (uint32_t*)(smf + VL_OFF);

  const int tid  = threadIdx.x;
  const int lane = tid & 31;
  const int warp = tid >> 5;
  const int g    = lane >> 2;
  const int tg   = lane & 3;
  const int bh   = blockIdx.y;
  const int b    = bh >> 4;
  const int h    = bh & 15;
  const int q0   = blockIdx.x << 7;

  const int wq = warp & 3;
  const int wk = warp >> 2;
  const int wm2 = warp & 3;
  const int wn2 = warp >> 2;

  const float* Qg = g_Q + ((size_t)bh * S_DIM + q0) * 64;
  const float* Kg = g_K + (size_t)bh * S_DIM * 64;
  const float* Vg = g_V + (size_t)bh * S_DIM * 64;

  {
#pragma unroll
    for (int i = 0; i < 8; i++) {
      const int idx = tid + i*256;
      const int row = idx >> 4;
      const int c4  = idx & 15;
      float4 v = *(const float4*)&Qg[(size_t)row*64 + c4*4];
      *(float4*)&Qs[row*QS_STRIDE + c4*4] = v;
    }
  }

  float co[2][4][4];
#pragma unroll
  for (int mt = 0; mt < 2; mt++)
#pragma unroll
    for (int nt = 0; nt < 4; nt++)
#pragma unroll
      for (int r = 0; r < 4; r++) co[mt][nt][r] = 0.0f;

  const uint32_t cbase = ((uint32_t)bh << 11) + (uint32_t)q0;

  for (int kt = 0; kt < 32; kt++) {
    __syncthreads();

    {
      const int r = tid >> 2;
      const float* krow = &Kg[(size_t)(kt*64 + r)*64];
      const int base = r*36;
#pragma unroll
      for (int i = 0; i < 4; i++) {
        const int d4 = (tid & 3)*4 + i;
        float4 v = *(const float4*)&krow[d4*4];
        uint32_t h0, m0_, l0, h1, m1, l1;
        split3(v.x, v.y, h0, m0_, l0);
        split3(v.z, v.w, h1, m1, l1);
        Kh[base + d4*2]     = h0;  Km[base + d4*2]     = m0_;  Kl[base + d4*2]     = l0;
        Kh[base + d4*2 + 1] = h1;  Km[base + d4*2 + 1] = m1;  Kl[base + d4*2 + 1] = l1;
      }
    }
    {
#pragma unroll
      for (int r = 0; r < 2; r++) {
        const int w  = tid + r*256;
        const int kp = w & 31;
        const int d0 = (w >> 5) * 4;
        const float* v0 = &Vg[(size_t)(kt*64 + 2*kp)*64 + d0];
        float4 a = *(const float4*)v0;
        float4 bvv = *(const float4*)(v0 + 64);
        float va[4] = {a.x, a.y, a.z, a.w};
        float vb[4] = {bvv.x, bvv.y, bvv.z, bvv.w};
#pragma unroll
        for (int e = 0; e < 4; e++) {
          uint32_t hp = pack_bf16(va[e], vb[e]);
          uint32_t lp = pack_bf16(va[e] - lo_f(hp), vb[e] - hi_f(hp));
          Vh[(d0+e)*36 + kp] = hp;
          Vl[(d0+e)*36 + kp] = lp;
        }
      }
    }
    __syncthreads();

    float c[2][4][4];
#pragma unroll
    for (int mt = 0; mt < 2; mt++)
#pragma unroll
      for (int nt = 0; nt < 4; nt++)
#pragma unroll
        for (int r = 0; r < 4; r++) c[mt][nt][r] = 0.0f;

#pragma unroll
    for (int c4 = 0; c4 < 4; c4++) {
      const int k0 = c4*16 + 2*tg;
      uint32_t Ah[2][4], Am[2][4], Al[2][4];
#pragma unroll
      for (int mt = 0; mt < 2; mt++) {
        const float* q0p = &Qs[(wq*32 + mt*16 + g)*QS_STRIDE];
        const float* q8p = q0p + 8*QS_STRIDE;
        float2 v00 = *(const float2*)&q0p[k0];
        float2 v01 = *(const float2*)&q8p[k0];
        float2 v10 = *(const float2*)&q0p[k0+8];
        float2 v11 = *(const float2*)&q8p[k0+8];
        split3(v00.x, v00.y, Ah[mt][0], Am[mt][0], Al[mt][0]);
        split3(v01.x, v01.y, Ah[mt][1], Am[mt][1], Al[mt][1]);
        split3(v10.x, v10.y, Ah[mt][2], Am[mt][2], Al[mt][2]);
        split3(v11.x, v11.y, Ah[mt][3], Am[mt][3], Al[mt][3]);
      }
#pragma unroll
      for (int nt = 0; nt < 4; nt++) {
        const int col = wk*32 + nt*8 + g;
        const int kb  = col*36 + c4*8;
        uint32_t Bh0 = Kh[kb+tg], Bh1 = Kh[kb+tg+4];
        uint32_t Bm0 = Km[kb+tg], Bm1 = Km[kb+tg+4];
        uint32_t Bl0 = Kl[kb+tg], Bl1 = Kl[kb+tg+4];
#pragma unroll
        for (int mt = 0; mt < 2; mt++) {
          mma_bf16(c[mt][nt], Ah[mt], Bh0, Bh1);
          mma_bf16(c[mt][nt], Ah[mt], Bm0, Bm1);
          mma_bf16(c[mt][nt], Am[mt], Bh0, Bh1);
          mma_bf16(c[mt][nt], Ah[mt], Bl0, Bl1);
          mma_bf16(c[mt][nt], Am[mt], Bm0, Bm1);
          mma_bf16(c[mt][nt], Al[mt], Bh0, Bh1);
        }
      }
    }

    const uint32_t ktk = (uint32_t)(kt*64);
#pragma unroll
    for (int mt = 0; mt < 2; mt++) {
      const int qA = wq*32 + mt*16 + g;
      const uint32_t row0 = (cbase + (uint32_t)qA) << 11;
      const uint32_t row8 = (cbase + (uint32_t)(qA+8)) << 11;
#pragma unroll
      for (int nt = 0; nt < 4; nt++) {
        const uint32_t kl = ktk + (uint32_t)(wk*32 + nt*8 + 2*tg);
        float p0 = 1.0f / (1.0f + expf(-c[mt][nt][0] * 0.125f));
        float p1 = 1.0f / (1.0f + expf(-c[mt][nt][1] * 0.125f));
        float p2 = 1.0f / (1.0f + expf(-c[mt][nt][2] * 0.125f));
        float p3 = 1.0f / (1.0f + expf(-c[mt][nt][3] * 0.125f));
        uint32_t b0 = jax_bits_k42(row0 + kl);
        uint32_t b1 = jax_bits_k42(row0 + kl + 1u);
        uint32_t b2 = jax_bits_k42(row8 + kl);
        uint32_t b3 = jax_bits_k42(row8 + kl + 1u);
        float u0 = __uint_as_float((b0 >> 9) | 0x3f800000u) - 1.0f;
        float u1 = __uint_as_float((b1 >> 9) | 0x3f800000u) - 1.0f;
        float u2 = __uint_as_float((b2 >> 9) | 0x3f800000u) - 1.0f;
        float u3 = __uint_as_float((b3 >> 9) | 0x3f800000u) - 1.0f;
        const int kp = wk*16 + nt*4 + tg;
        Pp[qA*36 + kp]     = pack_bf16(u0 < p0 ? 1.0f : 0.0f,
                                       u1 < p1 ? 1.0f : 0.0f);
        Pp[(qA+8)*36 + kp] = pack_bf16(u2 < p2 ? 1.0f : 0.0f,
                                       u3 < p3 ? 1.0f : 0.0f);
      }
    }
    __syncthreads();

#pragma unroll
    for (int c4 = 0; c4 < 4; c4++) {
      uint32_t a[2][4];
#pragma unroll
      for (int mt = 0; mt < 2; mt++) {
        const int row = wm2*32 + mt*16 + g;
        a[mt][0] = Pp[row    *36 + c4*8 + tg];
        a[mt][1] = Pp[(row+8)*36 + c4*8 + tg];
        a[mt][2] = Pp[row    *36 + c4*8 + tg + 4];
        a[mt][3] = Pp[(row+8)*36 + c4*8 + tg + 4];
      }
#pragma unroll
      for (int nt = 0; nt < 4; nt++) {
        const int d = wn2*32 + nt*8 + g;
        uint32_t bh0 = Vh[d*36 + c4*8 + tg];
        uint32_t bh1 = Vh[d*36 + c4*8 + tg + 4];
        uint32_t bl0 = Vl[d*36 + c4*8 + tg];
        uint32_t bl1 = Vl[d*36 + c4*8 + tg + 4];
#pragma unroll
        for (int mt = 0; mt < 2; mt++) {
          mma_bf16(co[mt][nt], a[mt], bh0, bh1);
          mma_bf16(co[mt][nt], a[mt], bl0, bl1);
        }
      }
    }
  }

#pragma unroll
  for (int mt = 0; mt < 2; mt++) {
    const int q = q0 + wm2*32 + mt*16 + g;
#pragma unroll
    for (int nt = 0; nt < 4; nt++) {
      const int d = wn2*32 + nt*8 + tg*2;
      size_t base = ((size_t)(b*S_DIM + q))*E_DIM + h*64 + d;
      *(float2*)&gAV[base] = make_float2(co[mt][nt][0], co[mt][nt][1]);
      *(float2*)&gAV[base + (size_t)8*E_DIM] =
          make_float2(co[mt][nt][2], co[mt][nt][3]);
    }
  }
}

// ===========================================================================
extern "C" void kernel_launch(void* const* d_in, const int* in_sizes, int n_in,
                              void* d_out, int out_size) {
  const float *x = nullptr, *qkv_w = nullptr, *qkv_b = nullptr;
  const float *out_w = nullptr, *out_b = nullptr;
  for (int i = 0; i < n_in; i++) {
    int sz = in_sizes[i];
    if (sz == B_DIM*S_DIM*E_DIM) { if (!x) x = (const float*)d_in[i]; }
    else if (sz == 3*E_DIM*E_DIM) qkv_w = (const float*)d_in[i];
    else if (sz == 3*E_DIM)       qkv_b = (const float*)d_in[i];
    else if (sz == E_DIM*E_DIM)   out_w = (const float*)d_in[i];
    else if (sz == E_DIM)         out_b = (const float*)d_in[i];
  }
  float* out = (float*)d_out;

  float* gav_ptr = nullptr;
  cudaGetSymbolAddress((void**)&gav_ptr, g_AV);

  // 1) QKV: tensor bf16 split, segmented RN accumulation, double-buffered.
  //    Q,K columns (0..2047): x6.  V columns (2048..3071): x3.
  qkv_tc<1><<<dim3(32, 32), 256>>>(x, qkv_w, qkv_b, 0);
  qkv_tc<0><<<dim3(16, 32), 256>>>(x, qkv_w, qkv_b, 2048);

  // 2) fused attention: tensor bf16x6 QK + threefry + tensor bf16x2 PV
  cudaFuncSetAttribute(attn_kernel, cudaFuncAttributeMaxDynamicSharedMemorySize,
                       ATTN_SMEM);
  attn_kernel<<<dim3(S_DIM/128, B_DIM*H_DIM), 256, ATTN_SMEM>>>(gav_ptr);

  // 3) out = AV @ out_w^T + out_b — tensor bf16x3
  bf16_proj<<<dim3(E_DIM/128, (B_DIM*S_DIM)/128), 256>>>(
      gav_ptr, out_w, out_b, out);
}

// round 11
// speedup vs baseline: 1.0582x; 1.0151x over previous
#include <cuda_runtime.h>
#include <cstdint>
#include <math.h>

#define B_DIM 2
#define H_DIM 16
#define S_DIM 2048
#define E_DIM 1024

// Scratch (allocation-free rule: device globals)
__device__ float g_V [B_DIM*H_DIM*S_DIM*64];          // [bh][s][d] fp32
__device__ float g_AV[B_DIM*S_DIM*E_DIM];             // [b][s][h*64+d]
// Pre-split Q/K: bf16x2 packed d-pairs, [comp][bh][s][dpair]
#define QP_COMP (B_DIM*H_DIM*S_DIM*32)
__device__ uint32_t g_Qp[3*QP_COMP];
__device__ uint32_t g_Kp[3*QP_COMP];

// ===========================================================================
// bf16 mma.sync helpers (base PTX, sm_80+)
// ===========================================================================
__device__ __forceinline__ uint32_t pack_bf16(float lo, float hi) {
  uint32_t r;  // PTX: first src -> upper half, second src -> lower half
  asm("cvt.rn.satfinite.bf16x2.f32 %0, %1, %2;" : "=r"(r) : "f"(hi), "f"(lo));
  return r;
}
__device__ __forceinline__ float lo_f(uint32_t u) {
  return __uint_as_float(u << 16);
}
__device__ __forceinline__ float hi_f(uint32_t u) {
  return __uint_as_float(u & 0xFFFF0000u);
}
__device__ __forceinline__ void split3(float fe, float fo,
                                       uint32_t& h, uint32_t& m, uint32_t& l) {
  h = pack_bf16(fe, fo);
  float re = fe - lo_f(h);
  float ro = fo - hi_f(h);
  m = pack_bf16(re, ro);
  l = pack_bf16(re - lo_f(m), ro - hi_f(m));
}
__device__ __forceinline__ void mma_bf16(float* c, const uint32_t* a,
                                         uint32_t b0, uint32_t b1) {
  asm volatile(
      "mma.sync.aligned.m16n8k16.row.col.f32.bf16.bf16.f32 "
      "{%0,%1,%2,%3},{%4,%5,%6,%7},{%8,%9},{%0,%1,%2,%3};"
      : "+f"(c[0]), "+f"(c[1]), "+f"(c[2]), "+f"(c[3])
      : "r"(a[0]), "r"(a[1]), "r"(a[2]), "r"(a[3]), "r"(b0), "r"(b1));
}

// ===========================================================================
// JAX partitionable-threefry random bits, key (0, 42).
// ===========================================================================
__device__ __forceinline__ uint32_t jax_bits_k42(uint32_t idx) {
  const uint32_t ks0 = 0u;
  const uint32_t ks1 = 42u;
  const uint32_t ks2 = 42u ^ 0x1BD11BDAu;
  uint32_t x0 = ks0;
  uint32_t x1 = idx + ks1;
#define TF_ROUND(r) { x0 += x1; x1 = __funnelshift_l(x1, x1, (r)); x1 ^= x0; }
  TF_ROUND(13) TF_ROUND(15) TF_ROUND(26) TF_ROUND(6)
  x0 += ks1; x1 += ks2 + 1u;
  TF_ROUND(17) TF_ROUND(29) TF_ROUND(16) TF_ROUND(24)
  x0 += ks2; x1 += ks0 + 2u;
  TF_ROUND(13) TF_ROUND(15) TF_ROUND(26) TF_ROUND(6)
  x0 += ks0; x1 += ks1 + 3u;
  TF_ROUND(17) TF_ROUND(29) TF_ROUND(16) TF_ROUND(24)
  x0 += ks1; x1 += ks2 + 4u;
  TF_ROUND(13) TF_ROUND(15) TF_ROUND(26) TF_ROUND(6)
  x0 += ks2; x1 += ks0 + 5u;
#undef TF_ROUND
  return x0 ^ x1;
}

// ===========================================================================
// Tensor QKV GEMM (r10 structure), SIX=1 epilogue now pre-splits Q/K into
// packed bf16x2 h/m/l gmem arrays (bit-identical split of the same values).
// ===========================================================================
template<int SIX>
__global__ void __launch_bounds__(256, 2)
qkv_tc(const float* __restrict__ A, const float* __restrict__ W,
       const float* __restrict__ bias, int ncol0) {
  __shared__ float As[2][16][132];
  __shared__ float Ws[2][16][68];
  const int tid  = threadIdx.x;
  const int lane = tid & 31;
  const int warp = tid >> 5;
  const int g    = lane >> 2;
  const int tg   = lane & 3;
  const int wm   = warp & 3;
  const int wn   = warp >> 2;
  const int m0   = blockIdx.y << 7;
  const int n0   = blockIdx.x << 6;

  const int lm = tid & 127;
  const int lk = (tid >> 7) << 3;
  const float* Ap = A + (size_t)(m0 + lm) * 1024 + lk;
  const int lmw = tid & 63;
  const int lkw = (tid >> 6) << 2;
  const float* Wp = W + (size_t)(ncol0 + n0 + lmw) * 1024 + lkw;

  float acc[2][4][4];
  float c[2][4][4];
#pragma unroll
  for (int mt = 0; mt < 2; mt++)
#pragma unroll
    for (int nt = 0; nt < 4; nt++)
#pragma unroll
      for (int r = 0; r < 4; r++) { acc[mt][nt][r] = 0.0f; c[mt][nt][r] = 0.0f; }

  {
    float4 a0 = *(const float4*)Ap;
    float4 a1 = *(const float4*)(Ap + 4);
    float4 w0 = *(const float4*)Wp;
    As[0][lk+0][lm] = a0.x; As[0][lk+1][lm] = a0.y;
    As[0][lk+2][lm] = a0.z; As[0][lk+3][lm] = a0.w;
    As[0][lk+4][lm] = a1.x; As[0][lk+5][lm] = a1.y;
    As[0][lk+6][lm] = a1.z; As[0][lk+7][lm] = a1.w;
    Ws[0][lkw+0][lmw] = w0.x; Ws[0][lkw+1][lmw] = w0.y;
    Ws[0][lkw+2][lmw] = w0.z; Ws[0][lkw+3][lmw] = w0.w;
  }
  __syncthreads();

  float4 av0, av1, wv;
  for (int it = 0; it < 64; it++) {
    const int buf = it & 1;
    const int k0  = it << 4;
    if (it + 1 < 64) {
      av0 = *(const float4*)(Ap + k0 + 16);
      av1 = *(const float4*)(Ap + k0 + 20);
      wv  = *(const float4*)(Wp + k0 + 16);
    }

    uint32_t Ah[2][4], Am[2][4], Al[2][4];
#pragma unroll
    for (int mt = 0; mt < 2; mt++) {
      const int r0 = wm*32 + mt*16 + g;
      const int ke = 2*tg;
#pragma unroll
      for (int p = 0; p < 4; p++) {
        const int kk = ke + ((p & 2) ? 8 : 0);
        const int rr = r0 + ((p & 1) ? 8 : 0);
        split3(As[buf][kk][rr], As[buf][kk+1][rr],
               Ah[mt][p], Am[mt][p], Al[mt][p]);
      }
    }

#pragma unroll
    for (int nt = 0; nt < 4; nt++) {
      const int n = wn*32 + nt*8 + g;
      const int ke = 2*tg;
      uint32_t Bh0, Bm0, Bl0, Bh1, Bm1, Bl1;
      split3(Ws[buf][ke][n],   Ws[buf][ke+1][n], Bh0, Bm0, Bl0);
      split3(Ws[buf][ke+8][n], Ws[buf][ke+9][n], Bh1, Bm1, Bl1);
#pragma unroll
      for (int mt = 0; mt < 2; mt++) {
        mma_bf16(c[mt][nt], Ah[mt], Bh0, Bh1);
        mma_bf16(c[mt][nt], Ah[mt], Bm0, Bm1);
        mma_bf16(c[mt][nt], Am[mt], Bh0, Bh1);
        if (SIX) {
          mma_bf16(c[mt][nt], Ah[mt], Bl0, Bl1);
          mma_bf16(c[mt][nt], Am[mt], Bm0, Bm1);
          mma_bf16(c[mt][nt], Al[mt], Bh0, Bh1);
        }
      }
    }

    if (it + 1 < 64) {
      const int nb = buf ^ 1;
      As[nb][lk+0][lm] = av0.x; As[nb][lk+1][lm] = av0.y;
      As[nb][lk+2][lm] = av0.z; As[nb][lk+3][lm] = av0.w;
      As[nb][lk+4][lm] = av1.x; As[nb][lk+5][lm] = av1.y;
      As[nb][lk+6][lm] = av1.z; As[nb][lk+7][lm] = av1.w;
      Ws[nb][lkw+0][lmw] = wv.x; Ws[nb][lkw+1][lmw] = wv.y;
      Ws[nb][lkw+2][lmw] = wv.z; Ws[nb][lkw+3][lmw] = wv.w;
      __syncthreads();
    }

    if ((it & 3) == 3) {
#pragma unroll
      for (int mt = 0; mt < 2; mt++)
#pragma unroll
        for (int nt = 0; nt < 4; nt++)
#pragma unroll
          for (int r = 0; r < 4; r++) {
            acc[mt][nt][r] += c[mt][nt][r];
            c[mt][nt][r] = 0.0f;
          }
    }
  }

  // Epilogue
#pragma unroll
  for (int nt = 0; nt < 4; nt++) {
    const int col = ncol0 + n0 + wn*32 + nt*8 + tg*2;
    const float bx = bias[col], by = bias[col+1];
    const int t  = col >> 10;
    const int hh = (col >> 6) & 15;
    const int d0 = col & 63;
#pragma unroll
    for (int mt = 0; mt < 2; mt++) {
      const int row = m0 + wm*32 + mt*16 + g;
      const int bb = row >> 11;
      const int s  = row & 2047;
      if (SIX) {
        // Q/K: split (value+bias) pairs, store packed h/m/l
        uint32_t* dst = (t == 0) ? g_Qp : g_Kp;
        const size_t base = ((size_t)(bb*H_DIM + hh)*S_DIM + s)*32 + (d0 >> 1);
#pragma unroll
        for (int rr = 0; rr < 2; rr++) {
          uint32_t h, m, l;
          split3(acc[mt][nt][rr*2] + bx, acc[mt][nt][rr*2+1] + by, h, m, l);
          size_t idx = base + (size_t)rr*8*32;
          dst[idx]             = h;
          dst[idx + QP_COMP]   = m;
          dst[idx + 2*QP_COMP] = l;
        }
      } else {
        float* dst = g_V;
        size_t base = ((size_t)(bb*H_DIM + hh)*S_DIM + s)*64 + d0;
        *(float2*)&dst[base] =
            make_float2(acc[mt][nt][0] + bx, acc[mt][nt][1] + by);
        *(float2*)&dst[base + 8*64] =
            make_float2(acc[mt][nt][2] + bx, acc[mt][nt][3] + by);
      }
    }
  }
}

// ===========================================================================
// bf16x3 tensor GEMM for the output projection (proven — unchanged).
// ===========================================================================
__global__ void __launch_bounds__(256, 2)
bf16_proj(const float* __restrict__ A, const float* __restrict__ W,
          const float* __restrict__ bias, float* __restrict__ C) {
  __shared__ float As[16][132];
  __shared__ float Ws[16][132];
  const int tid  = threadIdx.x;
  const int lane = tid & 31;
  const int warp = tid >> 5;
  const int g    = lane >> 2;
  const int tg   = lane & 3;
  const int wm   = warp & 3;
  const int wn   = warp >> 2;
  const int m0   = blockIdx.y << 7;
  const int n0   = blockIdx.x << 7;

  const int lm = tid & 127;
  const int lk = (tid >> 7) << 3;
  const float* Ap = A + (size_t)(m0 + lm) * 1024 + lk;
  const float* Wp = W + (size_t)(n0 + lm) * 1024 + lk;

  float c[2][8][4];
#pragma unroll
  for (int mt = 0; mt < 2; mt++)
#pragma unroll
    for (int nt = 0; nt < 8; nt++)
#pragma unroll
      for (int r = 0; r < 4; r++) c[mt][nt][r] = 0.0f;

  float4 av0 = *(const float4*)Ap;
  float4 av1 = *(const float4*)(Ap + 4);
  float4 wv0 = *(const float4*)Wp;
  float4 wv1 = *(const float4*)(Wp + 4);

  for (int k0 = 0; k0 < 1024; k0 += 16) {
    As[lk+0][lm] = av0.x; As[lk+1][lm] = av0.y;
    As[lk+2][lm] = av0.z; As[lk+3][lm] = av0.w;
    As[lk+4][lm] = av1.x; As[lk+5][lm] = av1.y;
    As[lk+6][lm] = av1.z; As[lk+7][lm] = av1.w;
    Ws[lk+0][lm] = wv0.x; Ws[lk+1][lm] = wv0.y;
    Ws[lk+2][lm] = wv0.z; Ws[lk+3][lm] = wv0.w;
    Ws[lk+4][lm] = wv1.x; Ws[lk+5][lm] = wv1.y;
    Ws[lk+6][lm] = wv1.z; Ws[lk+7][lm] = wv1.w;
    __syncthreads();
    if (k0 + 16 < 1024) {
      av0 = *(const float4*)(Ap + k0 + 16);
      av1 = *(const float4*)(Ap + k0 + 20);
      wv0 = *(const float4*)(Wp + k0 + 16);
      wv1 = *(const float4*)(Wp + k0 + 20);
    }

    uint32_t Ah[2][4], Am[2][4], Al[2][4];
#pragma unroll
    for (int mt = 0; mt < 2; mt++) {
      const int r0 = wm*32 + mt*16 + g;
      const int ke = 2*tg;
#pragma unroll
      for (int p = 0; p < 4; p++) {
        const int kk = ke + ((p & 2) ? 8 : 0);
        const int rr = r0 + ((p & 1) ? 8 : 0);
        split3(As[kk][rr], As[kk+1][rr], Ah[mt][p], Am[mt][p], Al[mt][p]);
      }
    }

#pragma unroll
    for (int nt = 0; nt < 8; nt++) {
      const int n = wn*64 + nt*8 + g;
      const int ke = 2*tg;
      uint32_t Bh0, Bm0, Bl0, Bh1, Bm1, Bl1;
      split3(Ws[ke][n],   Ws[ke+1][n], Bh0, Bm0, Bl0);
      split3(Ws[ke+8][n], Ws[ke+9][n], Bh1, Bm1, Bl1);
#pragma unroll
      for (int mt = 0; mt < 2; mt++) {
        mma_bf16(c[mt][nt], Ah[mt], Bh0, Bh1);
        mma_bf16(c[mt][nt], Ah[mt], Bm0, Bm1);
        mma_bf16(c[mt][nt], Am[mt], Bh0, Bh1);
      }
    }
    __syncthreads();
  }

#pragma unroll
  for (int nt = 0; nt < 8; nt++) {
    const int col = n0 + wn*64 + nt*8 + tg*2;
    const float bx = bias[col], by = bias[col+1];
#pragma unroll
    for (int mt = 0; mt < 2; mt++) {
      const int row = m0 + wm*32 + mt*16 + g;
      *(float2*)&C[(size_t)row     * E_DIM + col] =
          make_float2(c[mt][nt][0] + bx, c[mt][nt][1] + by);
      *(float2*)&C[(size_t)(row+8) * E_DIM + col] =
          make_float2(c[mt][nt][2] + bx, c[mt][nt][3] + by);
    }
  }
}

// ===========================================================================
// Fused attention v2: k-tile 32, all operands pre-split.
//   prologue: copy packed Q h/m/l (from g_Qp) into smem ONCE
//   per kt:   copy packed K h/m/l (pure uint4 copies), split V (x2)
//   QK bf16x6 -> sigmoid+threefry (identical math) -> Pp -> PV bf16x2
// smem u32 layout (stride 36 for frag-loaded arrays, 20 for Pp/V):
//   Qp 3x[128][36] | Kp 3x[32][36] | Vh/Vl [64][20] | Pp [128][20]
// ===========================================================================
#define QH0 0
#define QST 36
#define KH0 (3*128*36)              // 13824
#define KST 36
#define VH0 (KH0 + 3*32*36)         // 17280
#define VST 20
#define PP0 (VH0 + 2*64*20)         // 19840
#define PST 20
#define ATTN_SMEM ((PP0 + 128*20) * 4)   // 89600 bytes

__global__ void __launch_bounds__(256, 2)
attn_kernel(float* __restrict__ gAV) {
  extern __shared__ uint32_t sm[];
  const int tid  = threadIdx.x;
  const int lane = tid & 31;
  const int warp = tid >> 5;
  const int g    = lane >> 2;
  const int tg   = lane & 3;
  const int bh   = blockIdx.y;
  const int b    = bh >> 4;
  const int h    = bh & 15;
  const int q0   = blockIdx.x << 7;

  const int wq = warp & 3;     // QK q 32-group
  const int wk = warp >> 2;    // QK k 16-group
  const int wm2 = warp & 3;    // PV q 32-group
  const int wn2 = warp >> 2;   // PV d 32-group

  // Prologue: copy packed Q (3 comps x 128 rows x 32 pairs)
  {
    const uint32_t* src = g_Qp + ((size_t)bh * S_DIM + q0) * 32;
#pragma unroll
    for (int cc = 0; cc < 3; cc++) {
#pragma unroll
      for (int i = 0; i < 4; i++) {
        const int idx = tid + i*256;       // 1024 uint4s
        const int row = idx >> 3;
        const int p4  = idx & 7;
        uint4 v = *(const uint4*)(src + (size_t)cc*QP_COMP + (size_t)row*32 + p4*4);
        *(uint4*)&sm[QH0 + cc*(128*QST) + row*QST + p4*4] = v;
      }
    }
  }

  const float* Vg = g_V + (size_t)bh * S_DIM * 64;
  const uint32_t* Ksrc = g_Kp + (size_t)bh * S_DIM * 32;

  float co[2][4][4];
#pragma unroll
  for (int mt = 0; mt < 2; mt++)
#pragma unroll
    for (int nt = 0; nt < 4; nt++)
#pragma unroll
      for (int r = 0; r < 4; r++) co[mt][nt][r] = 0.0f;

  const uint32_t cbase = ((uint32_t)bh << 11) + (uint32_t)q0;

  for (int it = 0; it < 64; it++) {
    __syncthreads();   // previous PV / QK reads done before overwrite

    // stage K: 3 comps x 32 rows x 32 pairs, pure copies
    {
      const int row = tid >> 3;
      const int p4  = tid & 7;
      const uint32_t* s0 = Ksrc + (size_t)(it*32 + row)*32 + p4*4;
#pragma unroll
      for (int cc = 0; cc < 3; cc++) {
        uint4 v = *(const uint4*)(s0 + (size_t)cc*QP_COMP);
        *(uint4*)&sm[KH0 + cc*(32*KST) + row*KST + p4*4] = v;
      }
    }
    // stage V: split x2, pairs over k
    {
      const int kp = tid & 15;
      const int d0 = (tid >> 4) * 4;
      const float* v0 = &Vg[(size_t)(it*32 + 2*kp)*64 + d0];
      float4 a = *(const float4*)v0;
      float4 bvv = *(const float4*)(v0 + 64);
      float va[4] = {a.x, a.y, a.z, a.w};
      float vb[4] = {bvv.x, bvv.y, bvv.z, bvv.w};
#pragma unroll
      for (int e = 0; e < 4; e++) {
        uint32_t hp = pack_bf16(va[e], vb[e]);
        uint32_t lp = pack_bf16(va[e] - lo_f(hp), vb[e] - hi_f(hp));
        sm[VH0 + (d0+e)*VST + kp]             = hp;
        sm[VH0 + 64*VST + (d0+e)*VST + kp]    = lp;
      }
    }
    __syncthreads();

    // --- QK^T bf16x6: c[mt 2][nt 2][4], warp tile 32q x 16k ---
    float c[2][2][4];
#pragma unroll
    for (int mt = 0; mt < 2; mt++)
#pragma unroll
      for (int nt = 0; nt < 2; nt++)
#pragma unroll
        for (int r = 0; r < 4; r++) c[mt][nt][r] = 0.0f;

#pragma unroll
    for (int c4 = 0; c4 < 4; c4++) {
      uint32_t Ah[2][4], Am[2][4], Al[2][4];
#pragma unroll
      for (int mt = 0; mt < 2; mt++) {
        const int row = wq*32 + mt*16 + g;
        const int b0 = row*QST + c4*8;
        const int b8 = (row+8)*QST + c4*8;
        Ah[mt][0] = sm[QH0 + b0 + tg];
        Ah[mt][1] = sm[QH0 + b8 + tg];
        Ah[mt][2] = sm[QH0 + b0 + tg + 4];
        Ah[mt][3] = sm[QH0 + b8 + tg + 4];
        Am[mt][0] = sm[QH0 + 128*QST + b0 + tg];
        Am[mt][1] = sm[QH0 + 128*QST + b8 + tg];
        Am[mt][2] = sm[QH0 + 128*QST + b0 + tg + 4];
        Am[mt][3] = sm[QH0 + 128*QST + b8 + tg + 4];
        Al[mt][0] = sm[QH0 + 256*QST + b0 + tg];
        Al[mt][1] = sm[QH0 + 256*QST + b8 + tg];
        Al[mt][2] = sm[QH0 + 256*QST + b0 + tg + 4];
        Al[mt][3] = sm[QH0 + 256*QST + b8 + tg + 4];
      }
#pragma unroll
      for (int nt = 0; nt < 2; nt++) {
        const int col = wk*16 + nt*8 + g;
        const int kb  = col*KST + c4*8;
        uint32_t Bh0 = sm[KH0 + kb + tg],          Bh1 = sm[KH0 + kb + tg + 4];
        uint32_t Bm0 = sm[KH0 + 32*KST + kb + tg], Bm1 = sm[KH0 + 32*KST + kb + tg + 4];
        uint32_t Bl0 = sm[KH0 + 64*KST + kb + tg], Bl1 = sm[KH0 + 64*KST + kb + tg + 4];
#pragma unroll
        for (int mt = 0; mt < 2; mt++) {
          mma_bf16(c[mt][nt], Ah[mt], Bh0, Bh1);
          mma_bf16(c[mt][nt], Ah[mt], Bm0, Bm1);
          mma_bf16(c[mt][nt], Am[mt], Bh0, Bh1);
          mma_bf16(c[mt][nt], Ah[mt], Bl0, Bl1);
          mma_bf16(c[mt][nt], Am[mt], Bm0, Bm1);
          mma_bf16(c[mt][nt], Al[mt], Bh0, Bh1);
        }
      }
    }

    // --- sigmoid + threefry bernoulli (identical math); pack Pp ---
    const uint32_t ktk = (uint32_t)(it*32);
#pragma unroll
    for (int mt = 0; mt < 2; mt++) {
      const int qA = wq*32 + mt*16 + g;
      const uint32_t row0 = (cbase + (uint32_t)qA) << 11;
      const uint32_t row8 = (cbase + (uint32_t)(qA+8)) << 11;
#pragma unroll
      for (int nt = 0; nt < 2; nt++) {
        const uint32_t kl = ktk + (uint32_t)(wk*16 + nt*8 + 2*tg);
        float p0 = 1.0f / (1.0f + expf(-c[mt][nt][0] * 0.125f));
        float p1 = 1.0f / (1.0f + expf(-c[mt][nt][1] * 0.125f));
        float p2 = 1.0f / (1.0f + expf(-c[mt][nt][2] * 0.125f));
        float p3 = 1.0f / (1.0f + expf(-c[mt][nt][3] * 0.125f));
        uint32_t b0 = jax_bits_k42(row0 + kl);
        uint32_t b1 = jax_bits_k42(row0 + kl + 1u);
        uint32_t b2 = jax_bits_k42(row8 + kl);
        uint32_t b3 = jax_bits_k42(row8 + kl + 1u);
        float u0 = __uint_as_float((b0 >> 9) | 0x3f800000u) - 1.0f;
        float u1 = __uint_as_float((b1 >> 9) | 0x3f800000u) - 1.0f;
        float u2 = __uint_as_float((b2 >> 9) | 0x3f800000u) - 1.0f;
        float u3 = __uint_as_float((b3 >> 9) | 0x3f800000u) - 1.0f;
        const int kp = wk*8 + nt*4 + tg;
        sm[PP0 + qA*PST + kp]     = pack_bf16(u0 < p0 ? 1.0f : 0.0f,
                                              u1 < p1 ? 1.0f : 0.0f);
        sm[PP0 + (qA+8)*PST + kp] = pack_bf16(u2 < p2 ? 1.0f : 0.0f,
                                              u3 < p3 ? 1.0f : 0.0f);
      }
    }
    __syncthreads();

    // --- PV bf16x2: out[q][d] += P[q][k] * (Vh+Vl)[k][d] ---
#pragma unroll
    for (int c4 = 0; c4 < 2; c4++) {
      uint32_t a[2][4];
#pragma unroll
      for (int mt = 0; mt < 2; mt++) {
        const int row = wm2*32 + mt*16 + g;
        a[mt][0] = sm[PP0 + row    *PST + c4*8 + tg];
        a[mt][1] = sm[PP0 + (row+8)*PST + c4*8 + tg];
        a[mt][2] = sm[PP0 + row    *PST + c4*8 + tg + 4];
        a[mt][3] = sm[PP0 + (row+8)*PST + c4*8 + tg + 4];
      }
#pragma unroll
      for (int nt = 0; nt < 4; nt++) {
        const int d = wn2*32 + nt*8 + g;
        uint32_t bh0 = sm[VH0 + d*VST + c4*8 + tg];
        uint32_t bh1 = sm[VH0 + d*VST + c4*8 + tg + 4];
        uint32_t bl0 = sm[VH0 + 64*VST + d*VST + c4*8 + tg];
        uint32_t bl1 = sm[VH0 + 64*VST + d*VST + c4*8 + tg + 4];
#pragma unroll
        for (int mt = 0; mt < 2; mt++) {
          mma_bf16(co[mt][nt], a[mt], bh0, bh1);
          mma_bf16(co[mt][nt], a[mt], bl0, bl1);
        }
      }
    }
  }

  // Store PV c-fragments to g_AV [b][s][h*64+d]
#pragma unroll
  for (int mt = 0; mt < 2; mt++) {
    const int q = q0 + wm2*32 + mt*16 + g;
#pragma unroll
    for (int nt = 0; nt < 4; nt++) {
      const int d = wn2*32 + nt*8 + tg*2;
      size_t base = ((size_t)(b*S_DIM + q))*E_DIM + h*64 + d;
      *(float2*)&gAV[base] = make_float2(co[mt][nt][0], co[mt][nt][1]);
      *(float2*)&gAV[base + (size_t)8*E_DIM] =
          make_float2(co[mt][nt][2], co[mt][nt][3]);
    }
  }
}

// ===========================================================================
extern "C" void kernel_launch(void* const* d_in, const int* in_sizes, int n_in,
                              void* d_out, int out_size) {
  const float *x = nullptr, *qkv_w = nullptr, *qkv_b = nullptr;
  const float *out_w = nullptr, *out_b = nullptr;
  for (int i = 0; i < n_in; i++) {
    int sz = in_sizes[i];
    if (sz == B_DIM*S_DIM*E_DIM) { if (!x) x = (const float*)d_in[i]; }
    else if (sz == 3*E_DIM*E_DIM) qkv_w = (const float*)d_in[i];
    else if (sz == 3*E_DIM)       qkv_b = (const float*)d_in[i];
    else if (sz == E_DIM*E_DIM)   out_w = (const float*)d_in[i];
    else if (sz == E_DIM)         out_b = (const float*)d_in[i];
  }
  float* out = (float*)d_out;

  float* gav_ptr = nullptr;
  cudaGetSymbolAddress((void**)&gav_ptr, g_AV);

  // 1) QKV: Q,K cols x6 -> packed h/m/l gmem; V cols x3 -> fp32 g_V
  qkv_tc<1><<<dim3(32, 32), 256>>>(x, qkv_w, qkv_b, 0);
  qkv_tc<0><<<dim3(16, 32), 256>>>(x, qkv_w, qkv_b, 2048);

  // 2) fused attention v2 (k-tile 32, pre-split operands)
  cudaFuncSetAttribute(attn_kernel, cudaFuncAttributeMaxDynamicSharedMemorySize,
                       ATTN_SMEM);
  attn_kernel<<<dim3(S_DIM/128, B_DIM*H_DIM), 256, ATTN_SMEM>>>(gav_ptr);

  // 3) out = AV @ out_w^T + out_b — tensor bf16x3
  bf16_proj<<<dim3(E_DIM/128, (B_DIM*S_DIM)/128), 256>>>(
      gav_ptr, out_w, out_b, out);
}

// round 12
// speedup vs baseline: 1.2441x; 1.1757x over previous
#include <cuda_runtime.h>
#include <cstdint>
#include <math.h>

#define B_DIM 2
#define H_DIM 16
#define S_DIM 2048
#define E_DIM 1024
#define XROWS 4096            // B*S
#define KPAIRS 512            // 1024/2

// ---- device scratch (allocation-free rule) ----
__device__ float g_V [B_DIM*H_DIM*S_DIM*64];          // [bh][s][d] fp32
#define QP_COMP (B_DIM*H_DIM*S_DIM*32)
__device__ uint32_t g_Qp[3*QP_COMP];                  // packed Q h/m/l [comp][bh][s][dpair]
__device__ uint32_t g_Kp[3*QP_COMP];
// pre-split GEMM operands, layout [comp][kpair][row]
#define XC  (KPAIRS*XROWS)                            // 2,097,152
__device__ uint32_t g_xp [3*XC];                      // x split h/m/l
#define WQC (KPAIRS*3*E_DIM)                          // 1,572,864
__device__ uint32_t g_qwp[3*WQC];                     // qkv_w h/m/l
#define OWC (KPAIRS*E_DIM)                            // 524,288
__device__ uint32_t g_owp[2*OWC];                     // out_w h/m
#define AVC (KPAIRS*XROWS)
__device__ uint32_t g_avp[2*AVC];                     // AV h/m (written by attn)

// ===========================================================================
// bf16 helpers
// ===========================================================================
__device__ __forceinline__ uint32_t pack_bf16(float lo, float hi) {
  uint32_t r;
  asm("cvt.rn.satfinite.bf16x2.f32 %0, %1, %2;" : "=r"(r) : "f"(hi), "f"(lo));
  return r;
}
__device__ __forceinline__ float lo_f(uint32_t u) { return __uint_as_float(u << 16); }
__device__ __forceinline__ float hi_f(uint32_t u) { return __uint_as_float(u & 0xFFFF0000u); }
__device__ __forceinline__ void split3(float fe, float fo,
                                       uint32_t& h, uint32_t& m, uint32_t& l) {
  h = pack_bf16(fe, fo);
  float re = fe - lo_f(h);
  float ro = fo - hi_f(h);
  m = pack_bf16(re, ro);
  l = pack_bf16(re - lo_f(m), ro - hi_f(m));
}
__device__ __forceinline__ void mma_bf16(float* c, const uint32_t* a,
                                         uint32_t b0, uint32_t b1) {
  asm volatile(
      "mma.sync.aligned.m16n8k16.row.col.f32.bf16.bf16.f32 "
      "{%0,%1,%2,%3},{%4,%5,%6,%7},{%8,%9},{%0,%1,%2,%3};"
      : "+f"(c[0]), "+f"(c[1]), "+f"(c[2]), "+f"(c[3])
      : "r"(a[0]), "r"(a[1]), "r"(a[2]), "r"(a[3]), "r"(b0), "r"(b1));
}

// ===========================================================================
// JAX partitionable-threefry, key (0,42)
// ===========================================================================
__device__ __forceinline__ uint32_t jax_bits_k42(uint32_t idx) {
  const uint32_t ks0 = 0u;
  const uint32_t ks1 = 42u;
  const uint32_t ks2 = 42u ^ 0x1BD11BDAu;
  uint32_t x0 = ks0;
  uint32_t x1 = idx + ks1;
#define TF_ROUND(r) { x0 += x1; x1 = __funnelshift_l(x1, x1, (r)); x1 ^= x0; }
  TF_ROUND(13) TF_ROUND(15) TF_ROUND(26) TF_ROUND(6)
  x0 += ks1; x1 += ks2 + 1u;
  TF_ROUND(17) TF_ROUND(29) TF_ROUND(16) TF_ROUND(24)
  x0 += ks2; x1 += ks0 + 2u;
  TF_ROUND(13) TF_ROUND(15) TF_ROUND(26) TF_ROUND(6)
  x0 += ks0; x1 += ks1 + 3u;
  TF_ROUND(17) TF_ROUND(29) TF_ROUND(16) TF_ROUND(24)
  x0 += ks1; x1 += ks2 + 4u;
  TF_ROUND(13) TF_ROUND(15) TF_ROUND(26) TF_ROUND(6)
  x0 += ks2; x1 += ks0 + 5u;
#undef TF_ROUND
  return x0 ^ x1;
}

// ===========================================================================
// presplit: src [rows][1024] fp32 -> dst [NC][kpair][rows] packed bf16x2
// grid (rows/256, 512), block 256
// ===========================================================================
template<int NC>
__global__ void presplit(const float* __restrict__ src,
                         uint32_t* __restrict__ dst, int nrows) {
  const int row = blockIdx.x*256 + threadIdx.x;
  const int kp  = blockIdx.y;
  float2 v = *(const float2*)(src + (size_t)row*1024 + 2*kp);
  uint32_t h, m, l;
  split3(v.x, v.y, h, m, l);
  const size_t C = (size_t)KPAIRS * nrows;
  const size_t base = (size_t)kp*nrows + row;
  dst[base] = h;
  dst[base + C] = m;
  if (NC == 3) dst[base + 2*C] = l;
}

// ===========================================================================
// qkv GEMM from PRE-SPLIT operands. CTA 128x64, warp 32x32, BK=16 (8 kpairs),
// double-buffered, segmented RN accumulation (fold every 4 iters).
// SIX=1 (Q,K cols): x6, reads 3 comps. SIX=0 (V cols): x3, reads 2 comps.
// ===========================================================================
template<int SIX>
__global__ void __launch_bounds__(256, 2)
qkv_tc(const uint32_t* __restrict__ Apk, const uint32_t* __restrict__ Wpk,
       const float* __restrict__ bias, int ncol0) {
  const int NC = SIX ? 3 : 2;
  __shared__ uint32_t As[2][3*8*136];   // [buf][(comp*8+kp)*136 + row]
  __shared__ uint32_t Ws[2][3*8*72];    // [buf][(comp*8+kp)*72  + col]
  const int tid  = threadIdx.x;
  const int lane = tid & 31;
  const int warp = tid >> 5;
  const int g    = lane >> 2;
  const int tg   = lane & 3;
  const int wm   = warp & 3;
  const int wn   = warp >> 2;
  const int m0   = blockIdx.y << 7;
  const int n0   = blockIdx.x << 6;

  // staging maps
  const int akp = tid >> 5;            // 0..7
  const int ar4 = lane * 4;            // rows
  const int wkp = (tid >> 4) & 7;
  const int wc4 = (tid & 15) * 4;
  const bool wact = tid < 128;

  float acc[2][4][4], c[2][4][4];
#pragma unroll
  for (int mt = 0; mt < 2; mt++)
#pragma unroll
    for (int nt = 0; nt < 4; nt++)
#pragma unroll
      for (int r = 0; r < 4; r++) { acc[mt][nt][r] = 0.0f; c[mt][nt][r] = 0.0f; }

  // stage iter 0
#pragma unroll
  for (int cc = 0; cc < NC; cc++) {
    uint4 a = *(const uint4*)(Apk + (size_t)cc*XC + (size_t)akp*XROWS + m0 + ar4);
    *(uint4*)&As[0][(cc*8 + akp)*136 + ar4] = a;
    if (wact) {
      uint4 w = *(const uint4*)(Wpk + (size_t)cc*WQC + (size_t)wkp*(3*E_DIM) + ncol0 + n0 + wc4);
      *(uint4*)&Ws[0][(cc*8 + wkp)*72 + wc4] = w;
    }
  }
  __syncthreads();

  uint4 av[3], wv[3];
  for (int it = 0; it < 64; it++) {
    const int buf = it & 1;
    if (it + 1 < 64) {
#pragma unroll
      for (int cc = 0; cc < NC; cc++) {
        av[cc] = *(const uint4*)(Apk + (size_t)cc*XC +
                                 (size_t)((it+1)*8 + akp)*XROWS + m0 + ar4);
        if (wact)
          wv[cc] = *(const uint4*)(Wpk + (size_t)cc*WQC +
                                   (size_t)((it+1)*8 + wkp)*(3*E_DIM) + ncol0 + n0 + wc4);
      }
    }

    uint32_t Ah[2][4], Am[2][4], Al[2][4];
#pragma unroll
    for (int mt = 0; mt < 2; mt++) {
      const int r0 = wm*32 + mt*16 + g;
#pragma unroll
      for (int p = 0; p < 4; p++) {
        const int kp = tg + ((p & 2) ? 4 : 0);
        const int rr = r0 + ((p & 1) ? 8 : 0);
        Ah[mt][p] = As[buf][(0*8 + kp)*136 + rr];
        Am[mt][p] = As[buf][(1*8 + kp)*136 + rr];
        if (SIX) Al[mt][p] = As[buf][(2*8 + kp)*136 + rr];
      }
    }

#pragma unroll
    for (int nt = 0; nt < 4; nt++) {
      const int n = wn*32 + nt*8 + g;
      uint32_t Bh0 = Ws[buf][(0*8 + tg  )*72 + n];
      uint32_t Bh1 = Ws[buf][(0*8 + tg+4)*72 + n];
      uint32_t Bm0 = Ws[buf][(1*8 + tg  )*72 + n];
      uint32_t Bm1 = Ws[buf][(1*8 + tg+4)*72 + n];
      uint32_t Bl0 = 0, Bl1 = 0;
      if (SIX) { Bl0 = Ws[buf][(2*8 + tg)*72 + n]; Bl1 = Ws[buf][(2*8 + tg+4)*72 + n]; }
#pragma unroll
      for (int mt = 0; mt < 2; mt++) {
        mma_bf16(c[mt][nt], Ah[mt], Bh0, Bh1);
        mma_bf16(c[mt][nt], Ah[mt], Bm0, Bm1);
        mma_bf16(c[mt][nt], Am[mt], Bh0, Bh1);
        if (SIX) {
          mma_bf16(c[mt][nt], Ah[mt], Bl0, Bl1);
          mma_bf16(c[mt][nt], Am[mt], Bm0, Bm1);
          mma_bf16(c[mt][nt], Al[mt], Bh0, Bh1);
        }
      }
    }

    if (it + 1 < 64) {
      const int nb = buf ^ 1;
#pragma unroll
      for (int cc = 0; cc < NC; cc++) {
        *(uint4*)&As[nb][(cc*8 + akp)*136 + ar4] = av[cc];
        if (wact) *(uint4*)&Ws[nb][(cc*8 + wkp)*72 + wc4] = wv[cc];
      }
      __syncthreads();
    }

    if ((it & 3) == 3) {
#pragma unroll
      for (int mt = 0; mt < 2; mt++)
#pragma unroll
        for (int nt = 0; nt < 4; nt++)
#pragma unroll
          for (int r = 0; r < 4; r++) {
            acc[mt][nt][r] += c[mt][nt][r];
            c[mt][nt][r] = 0.0f;
          }
    }
  }

  // epilogue (identical to r11)
#pragma unroll
  for (int nt = 0; nt < 4; nt++) {
    const int col = ncol0 + n0 + wn*32 + nt*8 + tg*2;
    const float bx = bias[col], by = bias[col+1];
    const int t  = col >> 10;
    const int hh = (col >> 6) & 15;
    const int d0 = col & 63;
#pragma unroll
    for (int mt = 0; mt < 2; mt++) {
      const int row = m0 + wm*32 + mt*16 + g;
      const int bb = row >> 11;
      const int s  = row & 2047;
      if (SIX) {
        uint32_t* dst = (t == 0) ? g_Qp : g_Kp;
        const size_t base = ((size_t)(bb*H_DIM + hh)*S_DIM + s)*32 + (d0 >> 1);
#pragma unroll
        for (int rr = 0; rr < 2; rr++) {
          uint32_t h, m, l;
          split3(acc[mt][nt][rr*2] + bx, acc[mt][nt][rr*2+1] + by, h, m, l);
          size_t idx = base + (size_t)rr*8*32;
          dst[idx]             = h;
          dst[idx + QP_COMP]   = m;
          dst[idx + 2*QP_COMP] = l;
        }
      } else {
        size_t base = ((size_t)(bb*H_DIM + hh)*S_DIM + s)*64 + d0;
        *(float2*)&g_V[base] =
            make_float2(acc[mt][nt][0] + bx, acc[mt][nt][1] + by);
        *(float2*)&g_V[base + 8*64] =
            make_float2(acc[mt][nt][2] + bx, acc[mt][nt][3] + by);
      }
    }
  }
}

// ===========================================================================
// proj GEMM from pre-split AV (h/m) and out_w (h/m). CTA 128x128, warp 32x64.
// ===========================================================================
__global__ void __launch_bounds__(256, 2)
bf16_proj(const uint32_t* __restrict__ Apk, const uint32_t* __restrict__ Wpk,
          const float* __restrict__ bias, float* __restrict__ C) {
  __shared__ uint32_t As[2*8*136];   // [(comp*8+kp)*136 + row]
  __shared__ uint32_t Ws[2*8*136];
  const int tid  = threadIdx.x;
  const int lane = tid & 31;
  const int warp = tid >> 5;
  const int g    = lane >> 2;
  const int tg   = lane & 3;
  const int wm   = warp & 3;
  const int wn   = warp >> 2;
  const int m0   = blockIdx.y << 7;
  const int n0   = blockIdx.x << 7;

  const int kp = tid >> 5;
  const int r4 = lane * 4;

  float c[2][8][4];
#pragma unroll
  for (int mt = 0; mt < 2; mt++)
#pragma unroll
    for (int nt = 0; nt < 8; nt++)
#pragma unroll
      for (int r = 0; r < 4; r++) c[mt][nt][r] = 0.0f;

  uint4 av[2], wv[2];
#pragma unroll
  for (int cc = 0; cc < 2; cc++) {
    av[cc] = *(const uint4*)(Apk + (size_t)cc*AVC + (size_t)kp*XROWS + m0 + r4);
    wv[cc] = *(const uint4*)(Wpk + (size_t)cc*OWC + (size_t)kp*E_DIM + n0 + r4);
  }

  for (int it = 0; it < 64; it++) {
#pragma unroll
    for (int cc = 0; cc < 2; cc++) {
      *(uint4*)&As[(cc*8 + kp)*136 + r4] = av[cc];
      *(uint4*)&Ws[(cc*8 + kp)*136 + r4] = wv[cc];
    }
    __syncthreads();
    if (it + 1 < 64) {
#pragma unroll
      for (int cc = 0; cc < 2; cc++) {
        av[cc] = *(const uint4*)(Apk + (size_t)cc*AVC +
                                 (size_t)((it+1)*8 + kp)*XROWS + m0 + r4);
        wv[cc] = *(const uint4*)(Wpk + (size_t)cc*OWC +
                                 (size_t)((it+1)*8 + kp)*E_DIM + n0 + r4);
      }
    }

    uint32_t Ah[2][4], Am[2][4];
#pragma unroll
    for (int mt = 0; mt < 2; mt++) {
      const int r0 = wm*32 + mt*16 + g;
#pragma unroll
      for (int p = 0; p < 4; p++) {
        const int kq = tg + ((p & 2) ? 4 : 0);
        const int rr = r0 + ((p & 1) ? 8 : 0);
        Ah[mt][p] = As[(0*8 + kq)*136 + rr];
        Am[mt][p] = As[(1*8 + kq)*136 + rr];
      }
    }

#pragma unroll
    for (int nt = 0; nt < 8; nt++) {
      const int n = wn*64 + nt*8 + g;
      uint32_t Bh0 = Ws[(0*8 + tg  )*136 + n];
      uint32_t Bh1 = Ws[(0*8 + tg+4)*136 + n];
      uint32_t Bm0 = Ws[(1*8 + tg  )*136 + n];
      uint32_t Bm1 = Ws[(1*8 + tg+4)*136 + n];
#pragma unroll
      for (int mt = 0; mt < 2; mt++) {
        mma_bf16(c[mt][nt], Ah[mt], Bh0, Bh1);   // hh
        mma_bf16(c[mt][nt], Ah[mt], Bm0, Bm1);   // hm
        mma_bf16(c[mt][nt], Am[mt], Bh0, Bh1);   // mh
      }
    }
    __syncthreads();
  }

#pragma unroll
  for (int nt = 0; nt < 8; nt++) {
    const int col = n0 + wn*64 + nt*8 + tg*2;
    const float bx = bias[col], by = bias[col+1];
#pragma unroll
    for (int mt = 0; mt < 2; mt++) {
      const int row = m0 + wm*32 + mt*16 + g;
      *(float2*)&C[(size_t)row     * E_DIM + col] =
          make_float2(c[mt][nt][0] + bx, c[mt][nt][1] + by);
      *(float2*)&C[(size_t)(row+8) * E_DIM + col] =
          make_float2(c[mt][nt][2] + bx, c[mt][nt][3] + by);
    }
  }
}

// ===========================================================================
// Fused attention (r11 structure; epilogue now writes pre-split AV h/m)
// ===========================================================================
#define QH0 0
#define QST 36
#define KH0 (3*128*36)
#define KST 36
#define VH0 (KH0 + 3*32*36)
#define VST 20
#define PP0 (VH0 + 2*64*20)
#define PST 20
#define ATTN_SMEM ((PP0 + 128*20) * 4)   // 89600 bytes

__global__ void __launch_bounds__(256, 2)
attn_kernel() {
  extern __shared__ uint32_t sm[];
  const int tid  = threadIdx.x;
  const int lane = tid & 31;
  const int warp = tid >> 5;
  const int g    = lane >> 2;
  const int tg   = lane & 3;
  const int bh   = blockIdx.y;
  const int b    = bh >> 4;
  const int h    = bh & 15;
  const int q0   = blockIdx.x << 7;

  const int wq = warp & 3;
  const int wk = warp >> 2;
  const int wm2 = warp & 3;
  const int wn2 = warp >> 2;

  // Prologue: copy packed Q
  {
    const uint32_t* src = g_Qp + ((size_t)bh * S_DIM + q0) * 32;
#pragma unroll
    for (int cc = 0; cc < 3; cc++) {
#pragma unroll
      for (int i = 0; i < 4; i++) {
        const int idx = tid + i*256;
        const int row = idx >> 3;
        const int p4  = idx & 7;
        uint4 v = *(const uint4*)(src + (size_t)cc*QP_COMP + (size_t)row*32 + p4*4);
        *(uint4*)&sm[QH0 + cc*(128*QST) + row*QST + p4*4] = v;
      }
    }
  }

  const float* Vg = g_V + (size_t)bh * S_DIM * 64;
  const uint32_t* Ksrc = g_Kp + (size_t)bh * S_DIM * 32;

  float co[2][4][4];
#pragma unroll
  for (int mt = 0; mt < 2; mt++)
#pragma unroll
    for (int nt = 0; nt < 4; nt++)
#pragma unroll
      for (int r = 0; r < 4; r++) co[mt][nt][r] = 0.0f;

  const uint32_t cbase = ((uint32_t)bh << 11) + (uint32_t)q0;

  for (int it = 0; it < 64; it++) {
    __syncthreads();

    {
      const int row = tid >> 3;
      const int p4  = tid & 7;
      const uint32_t* s0 = Ksrc + (size_t)(it*32 + row)*32 + p4*4;
#pragma unroll
      for (int cc = 0; cc < 3; cc++) {
        uint4 v = *(const uint4*)(s0 + (size_t)cc*QP_COMP);
        *(uint4*)&sm[KH0 + cc*(32*KST) + row*KST + p4*4] = v;
      }
    }
    {
      const int kp = tid & 15;
      const int d0 = (tid >> 4) * 4;
      const float* v0 = &Vg[(size_t)(it*32 + 2*kp)*64 + d0];
      float4 a = *(const float4*)v0;
      float4 bvv = *(const float4*)(v0 + 64);
      float va[4] = {a.x, a.y, a.z, a.w};
      float vb[4] = {bvv.x, bvv.y, bvv.z, bvv.w};
#pragma unroll
      for (int e = 0; e < 4; e++) {
        uint32_t hp = pack_bf16(va[e], vb[e]);
        uint32_t lp = pack_bf16(va[e] - lo_f(hp), vb[e] - hi_f(hp));
        sm[VH0 + (d0+e)*VST + kp]          = hp;
        sm[VH0 + 64*VST + (d0+e)*VST + kp] = lp;
      }
    }
    __syncthreads();

    float c[2][2][4];
#pragma unroll
    for (int mt = 0; mt < 2; mt++)
#pragma unroll
      for (int nt = 0; nt < 2; nt++)
#pragma unroll
        for (int r = 0; r < 4; r++) c[mt][nt][r] = 0.0f;

#pragma unroll
    for (int c4 = 0; c4 < 4; c4++) {
      uint32_t Ah[2][4], Am[2][4], Al[2][4];
#pragma unroll
      for (int mt = 0; mt < 2; mt++) {
        const int row = wq*32 + mt*16 + g;
        const int b0 = row*QST + c4*8;
        const int b8 = (row+8)*QST + c4*8;
        Ah[mt][0] = sm[QH0 + b0 + tg];
        Ah[mt][1] = sm[QH0 + b8 + tg];
        Ah[mt][2] = sm[QH0 + b0 + tg + 4];
        Ah[mt][3] = sm[QH0 + b8 + tg + 4];
        Am[mt][0] = sm[QH0 + 128*QST + b0 + tg];
        Am[mt][1] = sm[QH0 + 128*QST + b8 + tg];
        Am[mt][2] = sm[QH0 + 128*QST + b0 + tg + 4];
        Am[mt][3] = sm[QH0 + 128*QST + b8 + tg + 4];
        Al[mt][0] = sm[QH0 + 256*QST + b0 + tg];
        Al[mt][1] = sm[QH0 + 256*QST + b8 + tg];
        Al[mt][2] = sm[QH0 + 256*QST + b0 + tg + 4];
        Al[mt][3] = sm[QH0 + 256*QST + b8 + tg + 4];
      }
#pragma unroll
      for (int nt = 0; nt < 2; nt++) {
        const int col = wk*16 + nt*8 + g;
        const int kb  = col*KST + c4*8;
        uint32_t Bh0 = sm[KH0 + kb + tg],          Bh1 = sm[KH0 + kb + tg + 4];
        uint32_t Bm0 = sm[KH0 + 32*KST + kb + tg], Bm1 = sm[KH0 + 32*KST + kb + tg + 4];
        uint32_t Bl0 = sm[KH0 + 64*KST + kb + tg], Bl1 = sm[KH0 + 64*KST + kb + tg + 4];
#pragma unroll
        for (int mt = 0; mt < 2; mt++) {
          mma_bf16(c[mt][nt], Ah[mt], Bh0, Bh1);
          mma_bf16(c[mt][nt], Ah[mt], Bm0, Bm1);
          mma_bf16(c[mt][nt], Am[mt], Bh0, Bh1);
          mma_bf16(c[mt][nt], Ah[mt], Bl0, Bl1);
          mma_bf16(c[mt][nt], Am[mt], Bm0, Bm1);
          mma_bf16(c[mt][nt], Al[mt], Bh0, Bh1);
        }
      }
    }

    const uint32_t ktk = (uint32_t)(it*32);
#pragma unroll
    for (int mt = 0; mt < 2; mt++) {
      const int qA = wq*32 + mt*16 + g;
      const uint32_t row0 = (cbase + (uint32_t)qA) << 11;
      const uint32_t row8 = (cbase + (uint32_t)(qA+8)) << 11;
#pragma unroll
      for (int nt = 0; nt < 2; nt++) {
        const uint32_t kl = ktk + (uint32_t)(wk*16 + nt*8 + 2*tg);
        float p0 = 1.0f / (1.0f + expf(-c[mt][nt][0] * 0.125f));
        float p1 = 1.0f / (1.0f + expf(-c[mt][nt][1] * 0.125f));
        float p2 = 1.0f / (1.0f + expf(-c[mt][nt][2] * 0.125f));
        float p3 = 1.0f / (1.0f + expf(-c[mt][nt][3] * 0.125f));
        uint32_t b0 = jax_bits_k42(row0 + kl);
        uint32_t b1 = jax_bits_k42(row0 + kl + 1u);
        uint32_t b2 = jax_bits_k42(row8 + kl);
        uint32_t b3 = jax_bits_k42(row8 + kl + 1u);
        float u0 = __uint_as_float((b0 >> 9) | 0x3f800000u) - 1.0f;
        float u1 = __uint_as_float((b1 >> 9) | 0x3f800000u) - 1.0f;
        float u2 = __uint_as_float((b2 >> 9) | 0x3f800000u) - 1.0f;
        float u3 = __uint_as_float((b3 >> 9) | 0x3f800000u) - 1.0f;
        const int kp = wk*8 + nt*4 + tg;
        sm[PP0 + qA*PST + kp]     = pack_bf16(u0 < p0 ? 1.0f : 0.0f,
                                              u1 < p1 ? 1.0f : 0.0f);
        sm[PP0 + (qA+8)*PST + kp] = pack_bf16(u2 < p2 ? 1.0f : 0.0f,
                                              u3 < p3 ? 1.0f : 0.0f);
      }
    }
    __syncthreads();

#pragma unroll
    for (int c4 = 0; c4 < 2; c4++) {
      uint32_t a[2][4];
#pragma unroll
      for (int mt = 0; mt < 2; mt++) {
        const int row = wm2*32 + mt*16 + g;
        a[mt][0] = sm[PP0 + row    *PST + c4*8 + tg];
        a[mt][1] = sm[PP0 + (row+8)*PST + c4*8 + tg];
        a[mt][2] = sm[PP0 + row    *PST + c4*8 + tg + 4];
        a[mt][3] = sm[PP0 + (row+8)*PST + c4*8 + tg + 4];
      }
#pragma unroll
      for (int nt = 0; nt < 4; nt++) {
        const int d = wn2*32 + nt*8 + g;
        uint32_t bh0 = sm[VH0 + d*VST + c4*8 + tg];
        uint32_t bh1 = sm[VH0 + d*VST + c4*8 + tg + 4];
        uint32_t bl0 = sm[VH0 + 64*VST + d*VST + c4*8 + tg];
        uint32_t bl1 = sm[VH0 + 64*VST + d*VST + c4*8 + tg + 4];
#pragma unroll
        for (int mt = 0; mt < 2; mt++) {
          mma_bf16(co[mt][nt], a[mt], bh0, bh1);
          mma_bf16(co[mt][nt], a[mt], bl0, bl1);
        }
      }
    }
  }

  // Epilogue: pre-split AV (h/m) into [comp][kpair][row]
#pragma unroll
  for (int mt = 0; mt < 2; mt++) {
    const int q = q0 + wm2*32 + mt*16 + g;
    const int row = b*S_DIM + q;
#pragma unroll
    for (int nt = 0; nt < 4; nt++) {
      const int d = wn2*32 + nt*8 + tg*2;
      const int kpair = h*32 + (d >> 1);
      uint32_t hh, mm, ll;
      split3(co[mt][nt][0], co[mt][nt][1], hh, mm, ll);
      g_avp[(size_t)kpair*XROWS + row]       = hh;
      g_avp[AVC + (size_t)kpair*XROWS + row] = mm;
      split3(co[mt][nt][2], co[mt][nt][3], hh, mm, ll);
      g_avp[(size_t)kpair*XROWS + row + 8]       = hh;
      g_avp[AVC + (size_t)kpair*XROWS + row + 8] = mm;
    }
  }
}

// ===========================================================================
extern "C" void kernel_launch(void* const* d_in, const int* in_sizes, int n_in,
                              void* d_out, int out_size) {
  const float *x = nullptr, *qkv_w = nullptr, *qkv_b = nullptr;
  const float *out_w = nullptr, *out_b = nullptr;
  for (int i = 0; i < n_in; i++) {
    int sz = in_sizes[i];
    if (sz == B_DIM*S_DIM*E_DIM) { if (!x) x = (const float*)d_in[i]; }
    else if (sz == 3*E_DIM*E_DIM) qkv_w = (const float*)d_in[i];
    else if (sz == 3*E_DIM)       qkv_b = (const float*)d_in[i];
    else if (sz == E_DIM*E_DIM)   out_w = (const float*)d_in[i];
    else if (sz == E_DIM)         out_b = (const float*)d_in[i];
  }
  float* out = (float*)d_out;

  uint32_t *xp, *qwp, *owp, *avp;
  cudaGetSymbolAddress((void**)&xp,  g_xp);
  cudaGetSymbolAddress((void**)&qwp, g_qwp);
  cudaGetSymbolAddress((void**)&owp, g_owp);
  cudaGetSymbolAddress((void**)&avp, g_avp);

  // 0) pre-split static operands
  presplit<3><<<dim3(XROWS/256, KPAIRS), 256>>>(x, xp, XROWS);
  presplit<3><<<dim3(3*E_DIM/256, KPAIRS), 256>>>(qkv_w, qwp, 3*E_DIM);
  presplit<2><<<dim3(E_DIM/256, KPAIRS), 256>>>(out_w, owp, E_DIM);

  // 1) QKV from pre-split operands
  qkv_tc<1><<<dim3(32, 32), 256>>>(xp, qwp, qkv_b, 0);
  qkv_tc<0><<<dim3(16, 32), 256>>>(xp, qwp, qkv_b, 2048);

  // 2) fused attention (epilogue pre-splits AV)
  cudaFuncSetAttribute(attn_kernel, cudaFuncAttributeMaxDynamicSharedMemorySize,
                       ATTN_SMEM);
  attn_kernel<<<dim3(S_DIM/128, B_DIM*H_DIM), 256, ATTN_SMEM>>>();

  // 3) out = AV @ out_w^T + out_b from pre-split operands
  bf16_proj<<<dim3(E_DIM/128, (B_DIM*S_DIM)/128), 256>>>(avp, owp, out_b, out);
}